// round 5
// baseline (speedup 1.0000x reference)
#include <cuda_runtime.h>
#include <math.h>

#define DD   1024
#define BB   16
#define TT   2048
#define NROW (TT*BB)          /* 32768 */
#define BD   (BB*DD)          /* 16384 */
#define SNB  128              /* scan blocks total */
#define GRP  4                /* independent batch groups */
#define BPG  32               /* blocks per group */

/* ------------- static device scratch (no allocations allowed) ------------- */
__device__ float    g_A[33554432];   /* x@Wx^T + b, [T*B, D], 128MB */
__device__ float    g_scale;         /* 0.99/(sigma+eps) */
__device__ __align__(128) unsigned g_flags[GRP][32];   /* one 128B line/group */

/* ====================== small PTX helpers ================================ */
__device__ __forceinline__ void ffma2(unsigned long long& acc,
                                      unsigned long long a, unsigned long long b) {
    asm("fma.rn.f32x2 %0, %1, %2, %0;" : "+l"(acc) : "l"(a), "l"(b));
}
__device__ __forceinline__ void ld_v2u64_nc(unsigned long long& lo, unsigned long long& hi,
                                            const void* p) {
    asm volatile("ld.global.nc.v2.u64 {%0,%1}, [%2];" : "=l"(lo), "=l"(hi) : "l"(p));
}
__device__ __forceinline__ unsigned f2tf(float f) {
    unsigned r;
    asm("cvt.rna.tf32.f32 %0, %1;" : "=r"(r) : "f"(f));
    return r;
}
__device__ __forceinline__ void mma_tf32(float* c, const unsigned* a, unsigned b0, unsigned b1) {
    asm volatile(
        "mma.sync.aligned.m16n8k8.row.col.f32.tf32.tf32.f32 "
        "{%0,%1,%2,%3},{%4,%5,%6,%7},{%8,%9},{%0,%1,%2,%3};"
        : "+f"(c[0]), "+f"(c[1]), "+f"(c[2]), "+f"(c[3])
        : "r"(a[0]), "r"(a[1]), "r"(a[2]), "r"(a[3]), "r"(b0), "r"(b1));
}

/* ===================== block-wide sum reduce ============================= */
__device__ __forceinline__ float blk_sum(float x, float* red, int tid) {
    #pragma unroll
    for (int o = 16; o; o >>= 1) x += __shfl_xor_sync(0xffffffffu, x, o);
    if ((tid & 31) == 0) red[tid >> 5] = x;
    __syncthreads();
    if (tid < 32) {
        float r = (tid < (int)(blockDim.x >> 5)) ? red[tid] : 0.f;
        #pragma unroll
        for (int o = 16; o; o >>= 1) r += __shfl_xor_sync(0xffffffffu, r, o);
        if (tid == 0) red[0] = r;
    }
    __syncthreads();
    float r = red[0];
    __syncthreads();
    return r;
}

/* ==================== fused spectral normalization ======================= */
struct P1024 { float v[1024]; };

__global__ void spectral_kernel(const float* __restrict__ Wh, P1024 u0) {
    __shared__ float u[DD], v[DD];
    __shared__ float red[32];
    int tid = threadIdx.x, lane = tid & 31, wid = tid >> 5;

    float x = u0.v[tid];
    float n0 = sqrtf(blk_sum(x * x, red, tid));   /* no eps: matches ref init */
    u[tid] = x / n0;
    __syncthreads();

    for (int it = 0; it < 3; it++) {
        /* v_raw = W^T u (coalesced column access) */
        float s = 0.f;
        #pragma unroll 4
        for (int k = 0; k < DD; k++) s = fmaf(__ldg(&Wh[(size_t)k * DD + tid]), u[k], s);
        float nv = sqrtf(blk_sum(s * s, red, tid)) + 1e-8f;
        v[tid] = s / nv;
        __syncthreads();

        /* u_raw = W v (warp-per-row) */
        for (int r = wid; r < DD; r += 32) {
            float p = 0.f;
            const float4* W4 = (const float4*)(Wh + (size_t)r * DD);
            const float4* v4 = (const float4*)v;
            #pragma unroll
            for (int i2 = 0; i2 < 8; i2++) {
                float4 w = __ldg(&W4[i2 * 32 + lane]);
                float4 vv = v4[i2 * 32 + lane];
                p = fmaf(w.x, vv.x, p); p = fmaf(w.y, vv.y, p);
                p = fmaf(w.z, vv.z, p); p = fmaf(w.w, vv.w, p);
            }
            #pragma unroll
            for (int o = 16; o; o >>= 1) p += __shfl_xor_sync(0xffffffffu, p, o);
            if (lane == 0) u[r] = p;
        }
        __syncthreads();
        float nu = sqrtf(blk_sum(u[tid] * u[tid], red, tid));
        if (it == 2 && tid == 0) {
            /* sigma = u.(Wv) = ||Wv||^2/(||Wv||+eps) since u = Wv/(||Wv||+eps) */
            float sig = nu * nu / (nu + 1e-8f);
            g_scale = 0.99f / (sig + 1e-8f);
        }
        u[tid] = u[tid] / (nu + 1e-8f);
        __syncthreads();
    }
}

/* ============================ init / reset =============================== */
__global__ void init_kernel(const float* __restrict__ h0, float* __restrict__ out_h) {
    int i = blockIdx.x * blockDim.x + threadIdx.x;
    if (i < BD) out_h[i] = h0[i];
    if (i < GRP * 32) g_flags[i >> 5][i & 31] = 0u;
}
__global__ void reset_kernel() {
    int i = threadIdx.x;
    if (i < GRP * 32) g_flags[i >> 5][i & 31] = 0u;
}

/* ===================== tf32 tensor-core GEMM ============================= */
/* C[M,N] = A[M,K]*B[N,K]^T, 128x128 tile, 8 warps, mma.m16n8k8.tf32.       */
/* MODE 0: g_A = acc + bias[n]    MODE 1: Cg = Hg * sigmoid(Zg + acc)       */
template <int MODE>
__global__ void __launch_bounds__(256, 2)
gemm_kernel(const float* __restrict__ Ag, const float* __restrict__ Bg,
            float* __restrict__ Cg, const float* __restrict__ bias,
            const float* __restrict__ Zg, const float* __restrict__ Hg,
            int m_off) {
    __shared__ unsigned As[128][36];
    __shared__ unsigned Bs[128][36];
    int tid = threadIdx.x, lane = tid & 31, wid = tid >> 5;
    int wm = wid >> 1, wn = wid & 1;
    int m0 = m_off + blockIdx.x * 128, n0 = blockIdx.y * 128;

    float acc[2][8][4];
    #pragma unroll
    for (int mt = 0; mt < 2; mt++)
        #pragma unroll
        for (int nt = 0; nt < 8; nt++)
            #pragma unroll
            for (int i = 0; i < 4; i++) acc[mt][nt][i] = 0.f;

    float4 abuf[4], bbuf[4];
    #pragma unroll
    for (int f = 0; f < 4; f++) {
        int q = f * 256 + tid, row = q >> 3, c4 = q & 7;
        abuf[f] = *(const float4*)&Ag[(size_t)(m0 + row) * DD + c4 * 4];
        bbuf[f] = *(const float4*)&Bg[(size_t)(n0 + row) * DD + c4 * 4];
    }

    for (int c = 0; c < 32; c++) {
        #pragma unroll
        for (int f = 0; f < 4; f++) {
            int q = f * 256 + tid, row = q >> 3, cc = (q & 7) * 4;
            *(uint4*)&As[row][cc] = make_uint4(f2tf(abuf[f].x), f2tf(abuf[f].y),
                                               f2tf(abuf[f].z), f2tf(abuf[f].w));
            *(uint4*)&Bs[row][cc] = make_uint4(f2tf(bbuf[f].x), f2tf(bbuf[f].y),
                                               f2tf(bbuf[f].z), f2tf(bbuf[f].w));
        }
        __syncthreads();
        if (c < 31) {
            int k0 = (c + 1) * 32;
            #pragma unroll
            for (int f = 0; f < 4; f++) {
                int q = f * 256 + tid, row = q >> 3, c4 = q & 7;
                abuf[f] = *(const float4*)&Ag[(size_t)(m0 + row) * DD + k0 + c4 * 4];
                bbuf[f] = *(const float4*)&Bg[(size_t)(n0 + row) * DD + k0 + c4 * 4];
            }
        }
        #pragma unroll
        for (int kk = 0; kk < 4; kk++) {
            unsigned a[2][4];
            int ar = wm * 32 + (lane >> 2);
            int kc = kk * 8 + (lane & 3);
            #pragma unroll
            for (int mt = 0; mt < 2; mt++) {
                int r = ar + mt * 16;
                a[mt][0] = As[r][kc];
                a[mt][1] = As[r + 8][kc];
                a[mt][2] = As[r][kc + 4];
                a[mt][3] = As[r + 8][kc + 4];
            }
            #pragma unroll
            for (int nt = 0; nt < 8; nt++) {
                int nc = wn * 64 + nt * 8 + (lane >> 2);
                unsigned b0 = Bs[nc][kc];
                unsigned b1 = Bs[nc][kc + 4];
                mma_tf32(acc[0][nt], a[0], b0, b1);
                mma_tf32(acc[1][nt], a[1], b0, b1);
            }
        }
        __syncthreads();
    }

    #pragma unroll
    for (int mt = 0; mt < 2; mt++) {
        int r = m0 + wm * 32 + mt * 16 + (lane >> 2);
        #pragma unroll
        for (int nt = 0; nt < 8; nt++) {
            int cc = n0 + wn * 64 + nt * 8 + (lane & 3) * 2;
            #pragma unroll
            for (int half = 0; half < 2; half++) {
                int rr = r + half * 8;
                size_t i0 = (size_t)rr * DD + cc;
                float v0 = acc[mt][nt][half * 2 + 0];
                float v1 = acc[mt][nt][half * 2 + 1];
                if (MODE == 0) {
                    g_A[i0]     = v0 + __ldg(&bias[cc]);
                    g_A[i0 + 1] = v1 + __ldg(&bias[cc + 1]);
                } else {
                    float h0v = Hg[i0], h1v = Hg[i0 + 1];
                    float g0 = 1.0f / (1.0f + __expf(-(Zg[i0] + v0)));
                    float g1 = 1.0f / (1.0f + __expf(-(Zg[i0 + 1] + v1)));
                    Cg[i0]     = h0v * g0;
                    Cg[i0 + 1] = h1v * g1;
                }
            }
        }
    }
}

/* ======================= persistent scan kernel ========================== */
/* 128 blocks = 4 groups x 32. Group g handles batches 4g..4g+3.            */
/* Block: 32 rows x 4 batches; warp: 4 rows x 4 batches, W_h in registers.  */
/* Barrier: per-group flag line (32 x u32 in one 128B line), ballot poll.   */
/* Reduce: merge tree, 16 shfl instead of 80.                               */
__device__ __forceinline__ float merge2(float a, float b, int B, int lane) {
    float send = (lane & B) ? a : b;
    float keep = (lane & B) ? b : a;
    return keep + __shfl_xor_sync(0xffffffffu, send, B);
}

__global__ void __launch_bounds__(256, 1)
scan_kernel(const float* __restrict__ Wh, float* __restrict__ out_h) {
    int tid = threadIdx.x, lane = tid & 31, wid = tid >> 5;
    int gid = blockIdx.x >> 5;         /* group 0..3 */
    int bin = blockIdx.x & 31;         /* block within group */
    int r0 = bin * 32 + wid * 4;       /* this warp's 4 rows */
    int gb = gid * 4;                  /* batch base */

    /* preload W rows into registers: w01 = (k,k+1), w23 = (k+2,k+3) */
    unsigned long long w01[4][8], w23[4][8];
    #pragma unroll
    for (int rr = 0; rr < 4; rr++)
        #pragma unroll
        for (int it = 0; it < 8; it++)
            ld_v2u64_nc(w01[rr][it], w23[rr][it],
                        Wh + (size_t)(r0 + rr) * DD + it * 128 + lane * 4);

    float s = g_scale;
    /* merge-tree output mapping: lane l ends with full sum of v[J(l)],
       J = b16 + 2*b8 + 4*b4 + 8*b2 (lanes l, l^1 share the same J) */
    int J = ((lane >> 4) & 1) | (((lane >> 3) & 1) << 1)
          | (((lane >> 2) & 1) << 2) | (((lane >> 1) & 1) << 3);
    int out_b   = gb + (J & 3);
    int out_row = r0 + (J >> 2);
    bool writer = (lane & 1) == 0;
    unsigned* flags = g_flags[gid];

    float a_val = __ldcg(&g_A[(size_t)out_b * DD + out_row]);   /* t = 0 */

    for (int t = 0; t < TT; t++) {
        const char* hb = (const char*)(out_h + (size_t)t * BD + (size_t)gb * DD);

        unsigned long long acc[4][4];
        #pragma unroll
        for (int rr = 0; rr < 4; rr++)
            #pragma unroll
            for (int b2 = 0; b2 < 4; b2++) acc[rr][b2] = 0ULL;

        #pragma unroll
        for (int it = 0; it < 8; it++) {
            ulonglong2 h[4];
            #pragma unroll
            for (int b2 = 0; b2 < 4; b2++)
                h[b2] = *(const ulonglong2*)(hb + (size_t)b2 * (DD * 4)
                                                + it * 512 + lane * 16);
            #pragma unroll
            for (int rr = 0; rr < 4; rr++)
                #pragma unroll
                for (int b2 = 0; b2 < 4; b2++) {
                    ffma2(acc[rr][b2], w01[rr][it], h[b2].x);
                    ffma2(acc[rr][b2], w23[rr][it], h[b2].y);
                }
        }

        /* prefetch next step's additive term (independent of h) */
        float a_next = 0.f;
        if (t + 1 < TT)
            a_next = __ldcg(&g_A[(size_t)(t + 1) * BD + (size_t)out_b * DD + out_row]);

        /* unpack packed accumulators */
        float v[16];
        #pragma unroll
        for (int rr = 0; rr < 4; rr++)
            #pragma unroll
            for (int b2 = 0; b2 < 4; b2++) {
                float lo, hi;
                asm("mov.b64 {%0,%1}, %2;" : "=f"(lo), "=f"(hi) : "l"(acc[rr][b2]));
                v[rr * 4 + b2] = lo + hi;
            }
        /* merge tree: 16 values x 32 lanes -> per-lane full sums, 16 shfl */
        float m[8], n4[4], p2[2], q;
        #pragma unroll
        for (int k = 0; k < 8; k++) m[k] = merge2(v[2 * k], v[2 * k + 1], 16, lane);
        #pragma unroll
        for (int k = 0; k < 4; k++) n4[k] = merge2(m[2 * k], m[2 * k + 1], 8, lane);
        #pragma unroll
        for (int k = 0; k < 2; k++) p2[k] = merge2(n4[2 * k], n4[2 * k + 1], 4, lane);
        q = merge2(p2[0], p2[1], 2, lane);
        q += __shfl_xor_sync(0xffffffffu, q, 1);

        if (writer) {
            float hv = tanhf(fmaf(s, q, a_val));
            out_h[(size_t)(t + 1) * BD + (size_t)out_b * DD + out_row] = hv;
        }

        if (t + 1 < TT) {
            __threadfence();               /* release h stores */
            __syncthreads();
            if (wid == 0) {
                if (lane == 0) *(volatile unsigned*)&flags[bin] = (unsigned)(t + 1);
                unsigned fv;
                do {
                    fv = *(volatile unsigned*)&flags[lane];
                } while (__any_sync(0xffffffffu, fv < (unsigned)(t + 1)));
                __threadfence();           /* acquire */
            }
            __syncthreads();
        }
        a_val = a_next;
    }
}

/* ================== host-side numpy-exact randn(1024) ==================== */
static void host_randn1024(float* out) {
    static unsigned mt[624];
    int pos;
    {
        unsigned s = 0u;
        for (int i = 0; i < 624; i++) {
            mt[i] = s;
            s = 1812433253u * (s ^ (s >> 30)) + (unsigned)(i + 1);
        }
        pos = 624;
    }
    auto next = [&]() -> unsigned {
        if (pos == 624) {
            for (int i = 0; i < 624; i++) {
                unsigned y = (mt[i] & 0x80000000u) | (mt[(i + 1) % 624] & 0x7fffffffu);
                mt[i] = mt[(i + 397) % 624] ^ (y >> 1) ^ ((y & 1u) ? 0x9908b0dfu : 0u);
            }
            pos = 0;
        }
        unsigned y = mt[pos++];
        y ^= y >> 11;
        y ^= (y << 7) & 0x9d2c5680u;
        y ^= (y << 15) & 0xefc60000u;
        y ^= y >> 18;
        return y;
    };
    auto nextDouble = [&]() -> double {
        unsigned a = next() >> 5, b = next() >> 6;
        return ((double)a * 67108864.0 + (double)b) / 9007199254740992.0;
    };
    bool has_g = false;
    double gcache = 0.0;
    for (int i = 0; i < DD; i++) {
        double val;
        if (has_g) { val = gcache; has_g = false; }
        else {
            double x1, x2, r2;
            do {
                x1 = 2.0 * nextDouble() - 1.0;
                x2 = 2.0 * nextDouble() - 1.0;
                r2 = x1 * x1 + x2 * x2;
            } while (r2 >= 1.0 || r2 == 0.0);
            double f = sqrt(-2.0 * log(r2) / r2);
            gcache = f * x1; has_g = true; val = f * x2;
        }
        out[i] = (float)val;
    }
}

/* ============================== launcher ================================= */
extern "C" void kernel_launch(void* const* d_in, const int* in_sizes, int n_in,
                              void* d_out, int out_size) {
    const float* x    = (const float*)d_in[0];
    const float* z    = (const float*)d_in[1];
    const float* h0   = (const float*)d_in[2];
    const float* Wx   = (const float*)d_in[3];
    const float* Wh   = (const float*)d_in[4];
    const float* Wg   = (const float*)d_in[5];
    const float* bias = (const float*)d_in[6];

    float* out   = (float*)d_out;
    float* outs  = out;                          /* [T, B, D]   */
    float* out_h = out + (size_t)NROW * DD;      /* [T+1, B, D] */
    const float* hs = out_h + BD;                /* h[1..T], row = t*B+b */

    static float u_host[DD];
    host_randn1024(u_host);
    P1024 u0;
    for (int i = 0; i < DD; i++) u0.v[i] = u_host[i];

    /* launch order fixed so ncu (-s 5 -c 1) captures the scan kernel */
    spectral_kernel<<<1, 1024>>>(Wh, u0);                                     /* 0 */
    init_kernel<<<16, 1024>>>(h0, out_h);                                     /* 1 */
    gemm_kernel<0><<<dim3(128, 8), 256>>>(x, Wx, nullptr, bias,
                                          nullptr, nullptr, 0);               /* 2 */
    gemm_kernel<0><<<dim3(128, 8), 256>>>(x, Wx, nullptr, bias,
                                          nullptr, nullptr, 16384);           /* 3 */
    reset_kernel<<<1, 128>>>();                                               /* 4 */
    scan_kernel<<<SNB, 256>>>(Wh, out_h);                                     /* 5 */
    gemm_kernel<1><<<dim3(256, 8), 256>>>(hs, Wg, outs, nullptr,
                                          z, hs, 0);                          /* 6 */
}

// round 6
// speedup vs baseline: 1.9824x; 1.9824x over previous
#include <cuda_runtime.h>
#include <math.h>

#define DD   1024
#define BB   16
#define TT   2048
#define NROW (TT*BB)          /* 32768 */
#define BD   (BB*DD)          /* 16384 */
#define SNB  128              /* scan blocks total */
#define GRP  4                /* independent batch groups */
#define BPG  32               /* blocks per group */

/* ------------- static device scratch (no allocations allowed) ------------- */
__device__ float    g_A[33554432];   /* x@Wx^T + b, [T*B, D], 128MB */
__device__ float    g_scale;         /* 0.99/(sigma+eps) */
__device__ unsigned g_cnt4[GRP * 32];   /* one line per group (stride 32) */
__device__ unsigned g_rel4[GRP * 32];

/* ====================== small PTX helpers ================================ */
__device__ __forceinline__ void ffma2(unsigned long long& acc,
                                      unsigned long long a, unsigned long long b) {
    asm("fma.rn.f32x2 %0, %1, %2, %0;" : "+l"(acc) : "l"(a), "l"(b));
}
__device__ __forceinline__ void ld_v2u64_nc(unsigned long long& lo, unsigned long long& hi,
                                            const void* p) {
    asm volatile("ld.global.nc.v2.u64 {%0,%1}, [%2];" : "=l"(lo), "=l"(hi) : "l"(p));
}
__device__ __forceinline__ unsigned f2tf(float f) {
    unsigned r;
    asm("cvt.rna.tf32.f32 %0, %1;" : "=r"(r) : "f"(f));
    return r;
}
__device__ __forceinline__ void mma_tf32(float* c, const unsigned* a, unsigned b0, unsigned b1) {
    asm volatile(
        "mma.sync.aligned.m16n8k8.row.col.f32.tf32.tf32.f32 "
        "{%0,%1,%2,%3},{%4,%5,%6,%7},{%8,%9},{%0,%1,%2,%3};"
        : "+f"(c[0]), "+f"(c[1]), "+f"(c[2]), "+f"(c[3])
        : "r"(a[0]), "r"(a[1]), "r"(a[2]), "r"(a[3]), "r"(b0), "r"(b1));
}

/* ===================== block-wide sum reduce ============================= */
__device__ __forceinline__ float blk_sum(float x, float* red, int tid) {
    #pragma unroll
    for (int o = 16; o; o >>= 1) x += __shfl_xor_sync(0xffffffffu, x, o);
    if ((tid & 31) == 0) red[tid >> 5] = x;
    __syncthreads();
    if (tid < 32) {
        float r = (tid < (int)(blockDim.x >> 5)) ? red[tid] : 0.f;
        #pragma unroll
        for (int o = 16; o; o >>= 1) r += __shfl_xor_sync(0xffffffffu, r, o);
        if (tid == 0) red[0] = r;
    }
    __syncthreads();
    float r = red[0];
    __syncthreads();
    return r;
}

/* ==================== fused spectral normalization ======================= */
struct P1024 { float v[1024]; };

__global__ void spectral_kernel(const float* __restrict__ Wh, P1024 u0) {
    __shared__ float u[DD], v[DD];
    __shared__ float red[32];
    int tid = threadIdx.x, lane = tid & 31, wid = tid >> 5;

    float x = u0.v[tid];
    float n0 = sqrtf(blk_sum(x * x, red, tid));   /* no eps: matches ref init */
    u[tid] = x / n0;
    __syncthreads();

    for (int it = 0; it < 3; it++) {
        /* v_raw = W^T u (coalesced column access) */
        float s = 0.f;
        #pragma unroll 4
        for (int k = 0; k < DD; k++) s = fmaf(__ldg(&Wh[(size_t)k * DD + tid]), u[k], s);
        float nv = sqrtf(blk_sum(s * s, red, tid)) + 1e-8f;
        v[tid] = s / nv;
        __syncthreads();

        /* u_raw = W v (warp-per-row) */
        for (int r = wid; r < DD; r += 32) {
            float p = 0.f;
            const float4* W4 = (const float4*)(Wh + (size_t)r * DD);
            const float4* v4 = (const float4*)v;
            #pragma unroll
            for (int i2 = 0; i2 < 8; i2++) {
                float4 w = __ldg(&W4[i2 * 32 + lane]);
                float4 vv = v4[i2 * 32 + lane];
                p = fmaf(w.x, vv.x, p); p = fmaf(w.y, vv.y, p);
                p = fmaf(w.z, vv.z, p); p = fmaf(w.w, vv.w, p);
            }
            #pragma unroll
            for (int o = 16; o; o >>= 1) p += __shfl_xor_sync(0xffffffffu, p, o);
            if (lane == 0) u[r] = p;
        }
        __syncthreads();
        float nu = sqrtf(blk_sum(u[tid] * u[tid], red, tid));
        if (it == 2 && tid == 0) {
            /* sigma = u.(Wv) = ||Wv||^2/(||Wv||+eps) since u = Wv/(||Wv||+eps) */
            float sig = nu * nu / (nu + 1e-8f);
            g_scale = 0.99f / (sig + 1e-8f);
        }
        u[tid] = u[tid] / (nu + 1e-8f);
        __syncthreads();
    }
}

/* ============================ init / reset =============================== */
__global__ void init_kernel(const float* __restrict__ h0, float* __restrict__ out_h) {
    int i = blockIdx.x * blockDim.x + threadIdx.x;
    if (i < BD) out_h[i] = h0[i];
    if (i < GRP) { g_cnt4[i * 32] = 0u; g_rel4[i * 32] = 0u; }
}
__global__ void reset_kernel() {
    int i = threadIdx.x;
    if (i < GRP) { g_cnt4[i * 32] = 0u; g_rel4[i * 32] = 0u; }
}

/* ===================== tf32 tensor-core GEMM ============================= */
/* C[M,N] = A[M,K]*B[N,K]^T, 128x128 tile, 8 warps, mma.m16n8k8.tf32.       */
/* MODE 0: g_A = acc + bias[n]    MODE 1: Cg = Hg * sigmoid(Zg + acc)       */
template <int MODE>
__global__ void __launch_bounds__(256, 2)
gemm_kernel(const float* __restrict__ Ag, const float* __restrict__ Bg,
            float* __restrict__ Cg, const float* __restrict__ bias,
            const float* __restrict__ Zg, const float* __restrict__ Hg,
            int m_off) {
    __shared__ unsigned As[128][36];
    __shared__ unsigned Bs[128][36];
    int tid = threadIdx.x, lane = tid & 31, wid = tid >> 5;
    int wm = wid >> 1, wn = wid & 1;
    int m0 = m_off + blockIdx.x * 128, n0 = blockIdx.y * 128;

    float acc[2][8][4];
    #pragma unroll
    for (int mt = 0; mt < 2; mt++)
        #pragma unroll
        for (int nt = 0; nt < 8; nt++)
            #pragma unroll
            for (int i = 0; i < 4; i++) acc[mt][nt][i] = 0.f;

    float4 abuf[4], bbuf[4];
    #pragma unroll
    for (int f = 0; f < 4; f++) {
        int q = f * 256 + tid, row = q >> 3, c4 = q & 7;
        abuf[f] = *(const float4*)&Ag[(size_t)(m0 + row) * DD + c4 * 4];
        bbuf[f] = *(const float4*)&Bg[(size_t)(n0 + row) * DD + c4 * 4];
    }

    for (int c = 0; c < 32; c++) {
        #pragma unroll
        for (int f = 0; f < 4; f++) {
            int q = f * 256 + tid, row = q >> 3, cc = (q & 7) * 4;
            *(uint4*)&As[row][cc] = make_uint4(f2tf(abuf[f].x), f2tf(abuf[f].y),
                                               f2tf(abuf[f].z), f2tf(abuf[f].w));
            *(uint4*)&Bs[row][cc] = make_uint4(f2tf(bbuf[f].x), f2tf(bbuf[f].y),
                                               f2tf(bbuf[f].z), f2tf(bbuf[f].w));
        }
        __syncthreads();
        if (c < 31) {
            int k0 = (c + 1) * 32;
            #pragma unroll
            for (int f = 0; f < 4; f++) {
                int q = f * 256 + tid, row = q >> 3, c4 = q & 7;
                abuf[f] = *(const float4*)&Ag[(size_t)(m0 + row) * DD + k0 + c4 * 4];
                bbuf[f] = *(const float4*)&Bg[(size_t)(n0 + row) * DD + k0 + c4 * 4];
            }
        }
        #pragma unroll
        for (int kk = 0; kk < 4; kk++) {
            unsigned a[2][4];
            int ar = wm * 32 + (lane >> 2);
            int kc = kk * 8 + (lane & 3);
            #pragma unroll
            for (int mt = 0; mt < 2; mt++) {
                int r = ar + mt * 16;
                a[mt][0] = As[r][kc];
                a[mt][1] = As[r + 8][kc];
                a[mt][2] = As[r][kc + 4];
                a[mt][3] = As[r + 8][kc + 4];
            }
            #pragma unroll
            for (int nt = 0; nt < 8; nt++) {
                int nc = wn * 64 + nt * 8 + (lane >> 2);
                unsigned b0 = Bs[nc][kc];
                unsigned b1 = Bs[nc][kc + 4];
                mma_tf32(acc[0][nt], a[0], b0, b1);
                mma_tf32(acc[1][nt], a[1], b0, b1);
            }
        }
        __syncthreads();
    }

    #pragma unroll
    for (int mt = 0; mt < 2; mt++) {
        int r = m0 + wm * 32 + mt * 16 + (lane >> 2);
        #pragma unroll
        for (int nt = 0; nt < 8; nt++) {
            int cc = n0 + wn * 64 + nt * 8 + (lane & 3) * 2;
            #pragma unroll
            for (int half = 0; half < 2; half++) {
                int rr = r + half * 8;
                size_t i0 = (size_t)rr * DD + cc;
                float v0 = acc[mt][nt][half * 2 + 0];
                float v1 = acc[mt][nt][half * 2 + 1];
                if (MODE == 0) {
                    g_A[i0]     = v0 + __ldg(&bias[cc]);
                    g_A[i0 + 1] = v1 + __ldg(&bias[cc + 1]);
                } else {
                    float h0v = Hg[i0], h1v = Hg[i0 + 1];
                    float g0 = 1.0f / (1.0f + __expf(-(Zg[i0] + v0)));
                    float g1 = 1.0f / (1.0f + __expf(-(Zg[i0 + 1] + v1)));
                    Cg[i0]     = h0v * g0;
                    Cg[i0 + 1] = h1v * g1;
                }
            }
        }
    }
}

/* ======================= persistent scan kernel ========================== */
/* 128 blocks = 4 groups x 32. Group g: batches 4g..4g+3.                   */
/* Block: 32 rows x 4 batches. K-SPLIT: 8 warps = 4 row-groups x 2 K-halves */
/* -> each warp reads only 8KB of h per step (512 L1 wavefronts/block, half */
/* of R4). W_h half-rows in registers. 32-value merge-tree reduce (31 shfl),*/
/* K-half partials combined through a 4x32 smem tile. Barrier: R4's proven  */
/* per-group atomic counter + single release-word poll by one thread.       */
__device__ __forceinline__ float merge2(float a, float b, int B, int lane) {
    float send = (lane & B) ? a : b;
    float keep = (lane & B) ? b : a;
    return keep + __shfl_xor_sync(0xffffffffu, send, B);
}

__global__ void __launch_bounds__(256, 1)
scan_kernel(const float* __restrict__ Wh, float* __restrict__ out_h) {
    __shared__ float comb[4][32];
    int tid = threadIdx.x, lane = tid & 31, wid = tid >> 5;
    int gid = blockIdx.x >> 5;         /* group 0..3 */
    int bin = blockIdx.x & 31;         /* block within group */
    int kh  = wid & 1;                 /* K-half 0/1 */
    int rg  = wid >> 1;                /* row group 0..3 */
    int r0  = bin * 32 + rg * 8;       /* warp's 8 rows */
    int gb  = gid * 4;                 /* batch base */
    int kb  = kh * 512;                /* K base */

    /* preload W half-rows: 8 rows x 512 K, lane covers k = kb+it*128+lane*4 */
    unsigned long long w01[8][4], w23[8][4];
    #pragma unroll
    for (int rr = 0; rr < 8; rr++)
        #pragma unroll
        for (int it = 0; it < 4; it++)
            ld_v2u64_nc(w01[rr][it], w23[rr][it],
                        Wh + (size_t)(r0 + rr) * DD + kb + it * 128 + lane * 4);

    float s = g_scale;
    /* bit-reversal lane->value map: lane ends with full sum of v[J] */
    int J = ((lane >> 4) & 1) | (((lane >> 3) & 1) << 1) | (((lane >> 2) & 1) << 2)
          | (((lane >> 1) & 1) << 3) | ((lane & 1) << 4);
    int out_b   = gb + (J & 3);
    int out_row = r0 + (J >> 2);
    unsigned* cnt = &g_cnt4[gid * 32];
    volatile unsigned* rel = (volatile unsigned*)&g_rel4[gid * 32];

    float a_val = (kh == 0) ? __ldcg(&g_A[(size_t)out_b * DD + out_row]) : 0.f;

    for (int t = 0; t < TT; t++) {
        const char* hb = (const char*)(out_h + (size_t)t * BD + (size_t)gb * DD + kb);

        unsigned long long acc[8][4];
        #pragma unroll
        for (int rr = 0; rr < 8; rr++)
            #pragma unroll
            for (int b2 = 0; b2 < 4; b2++) acc[rr][b2] = 0ULL;

        #pragma unroll
        for (int it = 0; it < 4; it++) {
            ulonglong2 h[4];
            #pragma unroll
            for (int b2 = 0; b2 < 4; b2++)
                h[b2] = *(const ulonglong2*)(hb + (size_t)b2 * (DD * 4)
                                                + it * 512 + lane * 16);
            #pragma unroll
            for (int rr = 0; rr < 8; rr++)
                #pragma unroll
                for (int b2 = 0; b2 < 4; b2++) {
                    ffma2(acc[rr][b2], w01[rr][it], h[b2].x);
                    ffma2(acc[rr][b2], w23[rr][it], h[b2].y);
                }
        }

        /* prefetch next step's additive term (independent of h) */
        float a_next = 0.f;
        if (kh == 0 && t + 1 < TT)
            a_next = __ldcg(&g_A[(size_t)(t + 1) * BD + (size_t)out_b * DD + out_row]);

        /* unpack packed accumulators -> 32 values */
        float v[32];
        #pragma unroll
        for (int rr = 0; rr < 8; rr++)
            #pragma unroll
            for (int b2 = 0; b2 < 4; b2++) {
                float lo, hi;
                asm("mov.b64 {%0,%1}, %2;" : "=f"(lo), "=f"(hi) : "l"(acc[rr][b2]));
                v[rr * 4 + b2] = lo + hi;
            }
        /* merge tree: 32 values x 32 lanes -> one full sum per lane (31 shfl) */
        float m16[16], m8[8], m4[4], m2[2], q;
        #pragma unroll
        for (int k = 0; k < 16; k++) m16[k] = merge2(v[2 * k], v[2 * k + 1], 16, lane);
        #pragma unroll
        for (int k = 0; k < 8; k++)  m8[k]  = merge2(m16[2 * k], m16[2 * k + 1], 8, lane);
        #pragma unroll
        for (int k = 0; k < 4; k++)  m4[k]  = merge2(m8[2 * k], m8[2 * k + 1], 4, lane);
        #pragma unroll
        for (int k = 0; k < 2; k++)  m2[k]  = merge2(m4[2 * k], m4[2 * k + 1], 2, lane);
        q = merge2(m2[0], m2[1], 1, lane);

        /* combine K-halves through smem */
        if (kh == 1) comb[rg][J] = q;
        __syncthreads();
        if (kh == 0) {
            float tot = q + comb[rg][J];
            float hv = tanhf(fmaf(s, tot, a_val));
            out_h[(size_t)(t + 1) * BD + (size_t)out_b * DD + out_row] = hv;
        }

        /* group barrier (R4): counter + release epoch, one poller per block */
        if (t + 1 < TT) {
            __threadfence();
            __syncthreads();
            if (tid == 0) {
                unsigned prev = atomicAdd(cnt, 1u);
                unsigned target = (unsigned)(t + 1) * (unsigned)BPG;
                if (prev + 1u == target) {
                    atomicExch((unsigned*)rel, (unsigned)(t + 1));
                } else {
                    while (*rel < (unsigned)(t + 1)) { }
                }
                __threadfence();
            }
            __syncthreads();
        }
        a_val = a_next;
    }
}

/* ================== host-side numpy-exact randn(1024) ==================== */
static void host_randn1024(float* out) {
    static unsigned mt[624];
    int pos;
    {
        unsigned s = 0u;
        for (int i = 0; i < 624; i++) {
            mt[i] = s;
            s = 1812433253u * (s ^ (s >> 30)) + (unsigned)(i + 1);
        }
        pos = 624;
    }
    auto next = [&]() -> unsigned {
        if (pos == 624) {
            for (int i = 0; i < 624; i++) {
                unsigned y = (mt[i] & 0x80000000u) | (mt[(i + 1) % 624] & 0x7fffffffu);
                mt[i] = mt[(i + 397) % 624] ^ (y >> 1) ^ ((y & 1u) ? 0x9908b0dfu : 0u);
            }
            pos = 0;
        }
        unsigned y = mt[pos++];
        y ^= y >> 11;
        y ^= (y << 7) & 0x9d2c5680u;
        y ^= (y << 15) & 0xefc60000u;
        y ^= y >> 18;
        return y;
    };
    auto nextDouble = [&]() -> double {
        unsigned a = next() >> 5, b = next() >> 6;
        return ((double)a * 67108864.0 + (double)b) / 9007199254740992.0;
    };
    bool has_g = false;
    double gcache = 0.0;
    for (int i = 0; i < DD; i++) {
        double val;
        if (has_g) { val = gcache; has_g = false; }
        else {
            double x1, x2, r2;
            do {
                x1 = 2.0 * nextDouble() - 1.0;
                x2 = 2.0 * nextDouble() - 1.0;
                r2 = x1 * x1 + x2 * x2;
            } while (r2 >= 1.0 || r2 == 0.0);
            double f = sqrt(-2.0 * log(r2) / r2);
            gcache = f * x1; has_g = true; val = f * x2;
        }
        out[i] = (float)val;
    }
}

/* ============================== launcher ================================= */
extern "C" void kernel_launch(void* const* d_in, const int* in_sizes, int n_in,
                              void* d_out, int out_size) {
    const float* x    = (const float*)d_in[0];
    const float* z    = (const float*)d_in[1];
    const float* h0   = (const float*)d_in[2];
    const float* Wx   = (const float*)d_in[3];
    const float* Wh   = (const float*)d_in[4];
    const float* Wg   = (const float*)d_in[5];
    const float* bias = (const float*)d_in[6];

    float* out   = (float*)d_out;
    float* outs  = out;                          /* [T, B, D]   */
    float* out_h = out + (size_t)NROW * DD;      /* [T+1, B, D] */
    const float* hs = out_h + BD;                /* h[1..T], row = t*B+b */

    static float u_host[DD];
    host_randn1024(u_host);
    P1024 u0;
    for (int i = 0; i < DD; i++) u0.v[i] = u_host[i];

    /* launch order fixed so ncu (-s 5 -c 1) captures the scan kernel */
    spectral_kernel<<<1, 1024>>>(Wh, u0);                                     /* 0 */
    init_kernel<<<16, 1024>>>(h0, out_h);                                     /* 1 */
    gemm_kernel<0><<<dim3(128, 8), 256>>>(x, Wx, nullptr, bias,
                                          nullptr, nullptr, 0);               /* 2 */
    gemm_kernel<0><<<dim3(128, 8), 256>>>(x, Wx, nullptr, bias,
                                          nullptr, nullptr, 16384);           /* 3 */
    reset_kernel<<<1, 32>>>();                                                /* 4 */
    scan_kernel<<<SNB, 256>>>(Wh, out_h);                                     /* 5 */
    gemm_kernel<1><<<dim3(256, 8), 256>>>(hs, Wg, outs, nullptr,
                                          z, hs, 0);                          /* 6 */
}

// round 7
// speedup vs baseline: 2.4436x; 1.2326x over previous
#include <cuda_runtime.h>
#include <math.h>

#define DD   1024
#define BB   16
#define TT   2048
#define NROW (TT*BB)          /* 32768 */
#define BD   (BB*DD)          /* 16384 */
#define SNB  128              /* scan blocks total */
#define GRP  4                /* independent batch groups */
#define BPG  32               /* blocks per group */

/* ------------- static device scratch (no allocations allowed) ------------- */
__device__ float    g_A[33554432];   /* x@Wx^T + b, [T*B, D], 128MB */
__device__ float    g_scale;         /* 0.99/(sigma+eps) */
__device__ unsigned g_cnt4[GRP * 32];   /* one 128B line per group (stride 32) */

/* ====================== small PTX helpers ================================ */
__device__ __forceinline__ void ffma2(unsigned long long& acc,
                                      unsigned long long a, unsigned long long b) {
    asm("fma.rn.f32x2 %0, %1, %2, %0;" : "+l"(acc) : "l"(a), "l"(b));
}
__device__ __forceinline__ void ld_v2u64_nc(unsigned long long& lo, unsigned long long& hi,
                                            const void* p) {
    asm volatile("ld.global.nc.v2.u64 {%0,%1}, [%2];" : "=l"(lo), "=l"(hi) : "l"(p));
}
__device__ __forceinline__ unsigned f2tf(float f) {
    unsigned r;
    asm("cvt.rna.tf32.f32 %0, %1;" : "=r"(r) : "f"(f));
    return r;
}
__device__ __forceinline__ void mma_tf32(float* c, const unsigned* a, unsigned b0, unsigned b1) {
    asm volatile(
        "mma.sync.aligned.m16n8k8.row.col.f32.tf32.tf32.f32 "
        "{%0,%1,%2,%3},{%4,%5,%6,%7},{%8,%9},{%0,%1,%2,%3};"
        : "+f"(c[0]), "+f"(c[1]), "+f"(c[2]), "+f"(c[3])
        : "r"(a[0]), "r"(a[1]), "r"(a[2]), "r"(a[3]), "r"(b0), "r"(b1));
}
/* fire-and-forget release arrive: memory system orders prior (bar-synced)
   CTA stores before the increment; the warp does NOT stall */
__device__ __forceinline__ void red_release_add(unsigned* p) {
    asm volatile("red.release.gpu.global.add.u32 [%0], 1;" :: "l"(p) : "memory");
}
__device__ __forceinline__ unsigned ld_acquire(const unsigned* p) {
    unsigned v;
    asm volatile("ld.acquire.gpu.global.u32 %0, [%1];" : "=r"(v) : "l"(p) : "memory");
    return v;
}
/* overflow-free fast tanh: err ~1e-6, way under tf32 noise */
__device__ __forceinline__ float fast_tanh(float x) {
    float e = __expf(-2.0f * fabsf(x));
    float r = __fdividef(1.0f - e, 1.0f + e);
    return copysignf(r, x);
}

/* ===================== block-wide sum reduce ============================= */
__device__ __forceinline__ float blk_sum(float x, float* red, int tid) {
    #pragma unroll
    for (int o = 16; o; o >>= 1) x += __shfl_xor_sync(0xffffffffu, x, o);
    if ((tid & 31) == 0) red[tid >> 5] = x;
    __syncthreads();
    if (tid < 32) {
        float r = (tid < (int)(blockDim.x >> 5)) ? red[tid] : 0.f;
        #pragma unroll
        for (int o = 16; o; o >>= 1) r += __shfl_xor_sync(0xffffffffu, r, o);
        if (tid == 0) red[0] = r;
    }
    __syncthreads();
    float r = red[0];
    __syncthreads();
    return r;
}

/* ==================== fused spectral normalization ======================= */
struct P1024 { float v[1024]; };

__global__ void spectral_kernel(const float* __restrict__ Wh, P1024 u0) {
    __shared__ float u[DD], v[DD];
    __shared__ float red[32];
    int tid = threadIdx.x, lane = tid & 31, wid = tid >> 5;

    float x = u0.v[tid];
    float n0 = sqrtf(blk_sum(x * x, red, tid));   /* no eps: matches ref init */
    u[tid] = x / n0;
    __syncthreads();

    for (int it = 0; it < 3; it++) {
        /* v_raw = W^T u (coalesced column access) */
        float s = 0.f;
        #pragma unroll 4
        for (int k = 0; k < DD; k++) s = fmaf(__ldg(&Wh[(size_t)k * DD + tid]), u[k], s);
        float nv = sqrtf(blk_sum(s * s, red, tid)) + 1e-8f;
        v[tid] = s / nv;
        __syncthreads();

        /* u_raw = W v (warp-per-row) */
        for (int r = wid; r < DD; r += 32) {
            float p = 0.f;
            const float4* W4 = (const float4*)(Wh + (size_t)r * DD);
            const float4* v4 = (const float4*)v;
            #pragma unroll
            for (int i2 = 0; i2 < 8; i2++) {
                float4 w = __ldg(&W4[i2 * 32 + lane]);
                float4 vv = v4[i2 * 32 + lane];
                p = fmaf(w.x, vv.x, p); p = fmaf(w.y, vv.y, p);
                p = fmaf(w.z, vv.z, p); p = fmaf(w.w, vv.w, p);
            }
            #pragma unroll
            for (int o = 16; o; o >>= 1) p += __shfl_xor_sync(0xffffffffu, p, o);
            if (lane == 0) u[r] = p;
        }
        __syncthreads();
        float nu = sqrtf(blk_sum(u[tid] * u[tid], red, tid));
        if (it == 2 && tid == 0) {
            /* sigma = u.(Wv) = ||Wv||^2/(||Wv||+eps) since u = Wv/(||Wv||+eps) */
            float sig = nu * nu / (nu + 1e-8f);
            g_scale = 0.99f / (sig + 1e-8f);
        }
        u[tid] = u[tid] / (nu + 1e-8f);
        __syncthreads();
    }
}

/* ============================ init / reset =============================== */
__global__ void init_kernel(const float* __restrict__ h0, float* __restrict__ out_h) {
    int i = blockIdx.x * blockDim.x + threadIdx.x;
    if (i < BD) out_h[i] = h0[i];
    if (i < GRP) g_cnt4[i * 32] = 0u;
}
__global__ void reset_kernel() {
    int i = threadIdx.x;
    if (i < GRP) g_cnt4[i * 32] = 0u;
}

/* ===================== tf32 tensor-core GEMM ============================= */
/* C[M,N] = A[M,K]*B[N,K]^T, 128x128 tile, 8 warps, mma.m16n8k8.tf32.       */
/* MODE 0: g_A = acc + bias[n]    MODE 1: Cg = Hg * sigmoid(Zg + acc)       */
template <int MODE>
__global__ void __launch_bounds__(256, 2)
gemm_kernel(const float* __restrict__ Ag, const float* __restrict__ Bg,
            float* __restrict__ Cg, const float* __restrict__ bias,
            const float* __restrict__ Zg, const float* __restrict__ Hg,
            int m_off) {
    __shared__ unsigned As[128][36];
    __shared__ unsigned Bs[128][36];
    int tid = threadIdx.x, lane = tid & 31, wid = tid >> 5;
    int wm = wid >> 1, wn = wid & 1;
    int m0 = m_off + blockIdx.x * 128, n0 = blockIdx.y * 128;

    float acc[2][8][4];
    #pragma unroll
    for (int mt = 0; mt < 2; mt++)
        #pragma unroll
        for (int nt = 0; nt < 8; nt++)
            #pragma unroll
            for (int i = 0; i < 4; i++) acc[mt][nt][i] = 0.f;

    float4 abuf[4], bbuf[4];
    #pragma unroll
    for (int f = 0; f < 4; f++) {
        int q = f * 256 + tid, row = q >> 3, c4 = q & 7;
        abuf[f] = *(const float4*)&Ag[(size_t)(m0 + row) * DD + c4 * 4];
        bbuf[f] = *(const float4*)&Bg[(size_t)(n0 + row) * DD + c4 * 4];
    }

    for (int c = 0; c < 32; c++) {
        #pragma unroll
        for (int f = 0; f < 4; f++) {
            int q = f * 256 + tid, row = q >> 3, cc = (q & 7) * 4;
            *(uint4*)&As[row][cc] = make_uint4(f2tf(abuf[f].x), f2tf(abuf[f].y),
                                               f2tf(abuf[f].z), f2tf(abuf[f].w));
            *(uint4*)&Bs[row][cc] = make_uint4(f2tf(bbuf[f].x), f2tf(bbuf[f].y),
                                               f2tf(bbuf[f].z), f2tf(bbuf[f].w));
        }
        __syncthreads();
        if (c < 31) {
            int k0 = (c + 1) * 32;
            #pragma unroll
            for (int f = 0; f < 4; f++) {
                int q = f * 256 + tid, row = q >> 3, c4 = q & 7;
                abuf[f] = *(const float4*)&Ag[(size_t)(m0 + row) * DD + k0 + c4 * 4];
                bbuf[f] = *(const float4*)&Bg[(size_t)(n0 + row) * DD + k0 + c4 * 4];
            }
        }
        #pragma unroll
        for (int kk = 0; kk < 4; kk++) {
            unsigned a[2][4];
            int ar = wm * 32 + (lane >> 2);
            int kc = kk * 8 + (lane & 3);
            #pragma unroll
            for (int mt = 0; mt < 2; mt++) {
                int r = ar + mt * 16;
                a[mt][0] = As[r][kc];
                a[mt][1] = As[r + 8][kc];
                a[mt][2] = As[r][kc + 4];
                a[mt][3] = As[r + 8][kc + 4];
            }
            #pragma unroll
            for (int nt = 0; nt < 8; nt++) {
                int nc = wn * 64 + nt * 8 + (lane >> 2);
                unsigned b0 = Bs[nc][kc];
                unsigned b1 = Bs[nc][kc + 4];
                mma_tf32(acc[0][nt], a[0], b0, b1);
                mma_tf32(acc[1][nt], a[1], b0, b1);
            }
        }
        __syncthreads();
    }

    #pragma unroll
    for (int mt = 0; mt < 2; mt++) {
        int r = m0 + wm * 32 + mt * 16 + (lane >> 2);
        #pragma unroll
        for (int nt = 0; nt < 8; nt++) {
            int cc = n0 + wn * 64 + nt * 8 + (lane & 3) * 2;
            #pragma unroll
            for (int half = 0; half < 2; half++) {
                int rr = r + half * 8;
                size_t i0 = (size_t)rr * DD + cc;
                float v0 = acc[mt][nt][half * 2 + 0];
                float v1 = acc[mt][nt][half * 2 + 1];
                if (MODE == 0) {
                    g_A[i0]     = v0 + __ldg(&bias[cc]);
                    g_A[i0 + 1] = v1 + __ldg(&bias[cc + 1]);
                } else {
                    float h0v = Hg[i0], h1v = Hg[i0 + 1];
                    float g0 = 1.0f / (1.0f + __expf(-(Zg[i0] + v0)));
                    float g1 = 1.0f / (1.0f + __expf(-(Zg[i0 + 1] + v1)));
                    Cg[i0]     = h0v * g0;
                    Cg[i0 + 1] = h1v * g1;
                }
            }
        }
    }
}

/* ======================= persistent scan kernel ========================== */
/* 128 blocks = 4 groups x 32. Group g: batches 4g..4g+3.                   */
/* Block: 32 rows x 4 batches; 8 warps = 4 row-groups x 2 K-halves.         */
/* W_h half-rows in registers. 32-value merge-tree reduce (31 shfl).        */
/* Barrier: red.release arrive (no stall) + ld.acquire poll on the counter  */
/* itself against monotonic target (no release word, no sense).             */
__device__ __forceinline__ float merge2(float a, float b, int B, int lane) {
    float send = (lane & B) ? a : b;
    float keep = (lane & B) ? b : a;
    return keep + __shfl_xor_sync(0xffffffffu, send, B);
}

__global__ void __launch_bounds__(256, 1)
scan_kernel(const float* __restrict__ Wh, float* __restrict__ out_h) {
    __shared__ float comb[4][32];
    int tid = threadIdx.x, lane = tid & 31, wid = tid >> 5;
    int gid = blockIdx.x >> 5;         /* group 0..3 */
    int bin = blockIdx.x & 31;         /* block within group */
    int kh  = wid & 1;                 /* K-half 0/1 */
    int rg  = wid >> 1;                /* row group 0..3 */
    int r0  = bin * 32 + rg * 8;       /* warp's 8 rows */
    int gb  = gid * 4;                 /* batch base */
    int kb  = kh * 512;                /* K base */

    /* preload W half-rows: 8 rows x 512 K, lane covers k = kb+it*128+lane*4 */
    unsigned long long w01[8][4], w23[8][4];
    #pragma unroll
    for (int rr = 0; rr < 8; rr++)
        #pragma unroll
        for (int it = 0; it < 4; it++)
            ld_v2u64_nc(w01[rr][it], w23[rr][it],
                        Wh + (size_t)(r0 + rr) * DD + kb + it * 128 + lane * 4);

    float s = g_scale;
    /* bit-reversal lane->value map: lane ends with full sum of v[J] */
    int J = ((lane >> 4) & 1) | (((lane >> 3) & 1) << 1) | (((lane >> 2) & 1) << 2)
          | (((lane >> 1) & 1) << 3) | ((lane & 1) << 4);
    int out_b   = gb + (J & 3);
    int out_row = r0 + (J >> 2);
    unsigned* cnt = &g_cnt4[gid * 32];

    float a_val = (kh == 0) ? __ldcg(&g_A[(size_t)out_b * DD + out_row]) : 0.f;

    for (int t = 0; t < TT; t++) {
        const char* hb = (const char*)(out_h + (size_t)t * BD + (size_t)gb * DD + kb);

        unsigned long long acc[8][4];
        #pragma unroll
        for (int rr = 0; rr < 8; rr++)
            #pragma unroll
            for (int b2 = 0; b2 < 4; b2++) acc[rr][b2] = 0ULL;

        #pragma unroll
        for (int it = 0; it < 4; it++) {
            ulonglong2 h[4];
            #pragma unroll
            for (int b2 = 0; b2 < 4; b2++)
                h[b2] = *(const ulonglong2*)(hb + (size_t)b2 * (DD * 4)
                                                + it * 512 + lane * 16);
            #pragma unroll
            for (int rr = 0; rr < 8; rr++)
                #pragma unroll
                for (int b2 = 0; b2 < 4; b2++) {
                    ffma2(acc[rr][b2], w01[rr][it], h[b2].x);
                    ffma2(acc[rr][b2], w23[rr][it], h[b2].y);
                }
        }

        /* prefetch next step's additive term (independent of h) */
        float a_next = 0.f;
        if (kh == 0 && t + 1 < TT)
            a_next = __ldcg(&g_A[(size_t)(t + 1) * BD + (size_t)out_b * DD + out_row]);

        /* unpack packed accumulators -> 32 values */
        float v[32];
        #pragma unroll
        for (int rr = 0; rr < 8; rr++)
            #pragma unroll
            for (int b2 = 0; b2 < 4; b2++) {
                float lo, hi;
                asm("mov.b64 {%0,%1}, %2;" : "=f"(lo), "=f"(hi) : "l"(acc[rr][b2]));
                v[rr * 4 + b2] = lo + hi;
            }
        /* merge tree: 32 values x 32 lanes -> one full sum per lane (31 shfl) */
        float m16[16], m8[8], m4[4], m2[2], q;
        #pragma unroll
        for (int k = 0; k < 16; k++) m16[k] = merge2(v[2 * k], v[2 * k + 1], 16, lane);
        #pragma unroll
        for (int k = 0; k < 8; k++)  m8[k]  = merge2(m16[2 * k], m16[2 * k + 1], 8, lane);
        #pragma unroll
        for (int k = 0; k < 4; k++)  m4[k]  = merge2(m8[2 * k], m8[2 * k + 1], 4, lane);
        #pragma unroll
        for (int k = 0; k < 2; k++)  m2[k]  = merge2(m4[2 * k], m4[2 * k + 1], 2, lane);
        q = merge2(m2[0], m2[1], 1, lane);

        /* combine K-halves through smem */
        if (kh == 1) comb[rg][J] = q;
        __syncthreads();
        if (kh == 0) {
            float tot = q + comb[rg][J];
            float hv = fast_tanh(fmaf(s, tot, a_val));
            out_h[(size_t)(t + 1) * BD + (size_t)out_b * DD + out_row] = hv;
        }

        /* group barrier: release-arrive (no stall) + acquire-poll on counter */
        if (t + 1 < TT) {
            __syncthreads();                    /* CTA stores done */
            if (tid == 0) {
                red_release_add(cnt);
                unsigned target = (unsigned)(t + 1) * (unsigned)BPG;
                while (ld_acquire(cnt) < target) { }
            }
            __syncthreads();                    /* propagate acquire CTA-wide */
        }
        a_val = a_next;
    }
}

/* ================== host-side numpy-exact randn(1024) ==================== */
static void host_randn1024(float* out) {
    static unsigned mt[624];
    int pos;
    {
        unsigned s = 0u;
        for (int i = 0; i < 624; i++) {
            mt[i] = s;
            s = 1812433253u * (s ^ (s >> 30)) + (unsigned)(i + 1);
        }
        pos = 624;
    }
    auto next = [&]() -> unsigned {
        if (pos == 624) {
            for (int i = 0; i < 624; i++) {
                unsigned y = (mt[i] & 0x80000000u) | (mt[(i + 1) % 624] & 0x7fffffffu);
                mt[i] = mt[(i + 397) % 624] ^ (y >> 1) ^ ((y & 1u) ? 0x9908b0dfu : 0u);
            }
            pos = 0;
        }
        unsigned y = mt[pos++];
        y ^= y >> 11;
        y ^= (y << 7) & 0x9d2c5680u;
        y ^= (y << 15) & 0xefc60000u;
        y ^= y >> 18;
        return y;
    };
    auto nextDouble = [&]() -> double {
        unsigned a = next() >> 5, b = next() >> 6;
        return ((double)a * 67108864.0 + (double)b) / 9007199254740992.0;
    };
    bool has_g = false;
    double gcache = 0.0;
    for (int i = 0; i < DD; i++) {
        double val;
        if (has_g) { val = gcache; has_g = false; }
        else {
            double x1, x2, r2;
            do {
                x1 = 2.0 * nextDouble() - 1.0;
                x2 = 2.0 * nextDouble() - 1.0;
                r2 = x1 * x1 + x2 * x2;
            } while (r2 >= 1.0 || r2 == 0.0);
            double f = sqrt(-2.0 * log(r2) / r2);
            gcache = f * x1; has_g = true; val = f * x2;
        }
        out[i] = (float)val;
    }
}

/* ============================== launcher ================================= */
extern "C" void kernel_launch(void* const* d_in, const int* in_sizes, int n_in,
                              void* d_out, int out_size) {
    const float* x    = (const float*)d_in[0];
    const float* z    = (const float*)d_in[1];
    const float* h0   = (const float*)d_in[2];
    const float* Wx   = (const float*)d_in[3];
    const float* Wh   = (const float*)d_in[4];
    const float* Wg   = (const float*)d_in[5];
    const float* bias = (const float*)d_in[6];

    float* out   = (float*)d_out;
    float* outs  = out;                          /* [T, B, D]   */
    float* out_h = out + (size_t)NROW * DD;      /* [T+1, B, D] */
    const float* hs = out_h + BD;                /* h[1..T], row = t*B+b */

    static float u_host[DD];
    host_randn1024(u_host);
    P1024 u0;
    for (int i = 0; i < DD; i++) u0.v[i] = u_host[i];

    /* launch order fixed so ncu (-s 5 -c 1) captures the scan kernel */
    spectral_kernel<<<1, 1024>>>(Wh, u0);                                     /* 0 */
    init_kernel<<<16, 1024>>>(h0, out_h);                                     /* 1 */
    gemm_kernel<0><<<dim3(128, 8), 256>>>(x, Wx, nullptr, bias,
                                          nullptr, nullptr, 0);               /* 2 */
    gemm_kernel<0><<<dim3(128, 8), 256>>>(x, Wx, nullptr, bias,
                                          nullptr, nullptr, 16384);           /* 3 */
    reset_kernel<<<1, 32>>>();                                                /* 4 */
    scan_kernel<<<SNB, 256>>>(Wh, out_h);                                     /* 5 */
    gemm_kernel<1><<<dim3(256, 8), 256>>>(hs, Wg, outs, nullptr,
                                          z, hs, 0);                          /* 6 */
}

// round 8
// speedup vs baseline: 3.0257x; 1.2382x over previous
#include <cuda_runtime.h>
#include <cuda_fp16.h>
#include <math.h>

#define DD   1024
#define BB   16
#define TT   2048
#define NROW (TT*BB)          /* 32768 */
#define BD   (BB*DD)          /* 16384 */
#define SNB  128              /* scan blocks total */
#define GRP  4                /* independent batch groups */
#define BPG  32               /* blocks per group */

/* ------------- static device scratch (no allocations allowed) ------------- */
__device__ float    g_A[33554432];            /* x@Wx^T + b, [T*B, D], 128MB */
__device__ float    g_scale;                  /* 0.99/(sigma+eps) */
__device__ unsigned g_cnt4[GRP * 32];         /* one 128B line per group */
__device__ __half   g_Wh16[DD * DD];          /* fp16 of (scale * W_h), 2MB */
__device__ __half   g_h16[(TT + 1) * BD];     /* fp16 shadow of h, 67MB */

/* ====================== small PTX helpers ================================ */
__device__ __forceinline__ unsigned f2tf(float f) {
    unsigned r;
    asm("cvt.rna.tf32.f32 %0, %1;" : "=r"(r) : "f"(f));
    return r;
}
__device__ __forceinline__ void mma_tf32(float* c, const unsigned* a, unsigned b0, unsigned b1) {
    asm volatile(
        "mma.sync.aligned.m16n8k8.row.col.f32.tf32.tf32.f32 "
        "{%0,%1,%2,%3},{%4,%5,%6,%7},{%8,%9},{%0,%1,%2,%3};"
        : "+f"(c[0]), "+f"(c[1]), "+f"(c[2]), "+f"(c[3])
        : "r"(a[0]), "r"(a[1]), "r"(a[2]), "r"(a[3]), "r"(b0), "r"(b1));
}
__device__ __forceinline__ void mma_fp16(float* c, const unsigned* a,
                                         unsigned b0, unsigned b1) {
    asm volatile(
        "mma.sync.aligned.m16n8k16.row.col.f32.f16.f16.f32 "
        "{%0,%1,%2,%3},{%4,%5,%6,%7},{%8,%9},{%0,%1,%2,%3};"
        : "+f"(c[0]), "+f"(c[1]), "+f"(c[2]), "+f"(c[3])
        : "r"(a[0]), "r"(a[1]), "r"(a[2]), "r"(a[3]), "r"(b0), "r"(b1));
}
/* fire-and-forget release arrive */
__device__ __forceinline__ void red_release_add(unsigned* p) {
    asm volatile("red.release.gpu.global.add.u32 [%0], 1;" :: "l"(p) : "memory");
}
__device__ __forceinline__ unsigned ld_acquire(const unsigned* p) {
    unsigned v;
    asm volatile("ld.acquire.gpu.global.u32 %0, [%1];" : "=r"(v) : "l"(p) : "memory");
    return v;
}
/* overflow-free fast tanh */
__device__ __forceinline__ float fast_tanh(float x) {
    float e = __expf(-2.0f * fabsf(x));
    float r = __fdividef(1.0f - e, 1.0f + e);
    return copysignf(r, x);
}

/* ===================== block-wide sum reduce ============================= */
__device__ __forceinline__ float blk_sum(float x, float* red, int tid) {
    #pragma unroll
    for (int o = 16; o; o >>= 1) x += __shfl_xor_sync(0xffffffffu, x, o);
    if ((tid & 31) == 0) red[tid >> 5] = x;
    __syncthreads();
    if (tid < 32) {
        float r = (tid < (int)(blockDim.x >> 5)) ? red[tid] : 0.f;
        #pragma unroll
        for (int o = 16; o; o >>= 1) r += __shfl_xor_sync(0xffffffffu, r, o);
        if (tid == 0) red[0] = r;
    }
    __syncthreads();
    float r = red[0];
    __syncthreads();
    return r;
}

/* ==================== fused spectral normalization ======================= */
struct P1024 { float v[1024]; };

__global__ void spectral_kernel(const float* __restrict__ Wh, P1024 u0) {
    __shared__ float u[DD], v[DD];
    __shared__ float red[32];
    int tid = threadIdx.x, lane = tid & 31, wid = tid >> 5;

    float x = u0.v[tid];
    float n0 = sqrtf(blk_sum(x * x, red, tid));   /* no eps: matches ref init */
    u[tid] = x / n0;
    __syncthreads();

    for (int it = 0; it < 3; it++) {
        /* v_raw = W^T u (coalesced column access) */
        float s = 0.f;
        #pragma unroll 4
        for (int k = 0; k < DD; k++) s = fmaf(__ldg(&Wh[(size_t)k * DD + tid]), u[k], s);
        float nv = sqrtf(blk_sum(s * s, red, tid)) + 1e-8f;
        v[tid] = s / nv;
        __syncthreads();

        /* u_raw = W v (warp-per-row) */
        for (int r = wid; r < DD; r += 32) {
            float p = 0.f;
            const float4* W4 = (const float4*)(Wh + (size_t)r * DD);
            const float4* v4 = (const float4*)v;
            #pragma unroll
            for (int i2 = 0; i2 < 8; i2++) {
                float4 w = __ldg(&W4[i2 * 32 + lane]);
                float4 vv = v4[i2 * 32 + lane];
                p = fmaf(w.x, vv.x, p); p = fmaf(w.y, vv.y, p);
                p = fmaf(w.z, vv.z, p); p = fmaf(w.w, vv.w, p);
            }
            #pragma unroll
            for (int o = 16; o; o >>= 1) p += __shfl_xor_sync(0xffffffffu, p, o);
            if (lane == 0) u[r] = p;
        }
        __syncthreads();
        float nu = sqrtf(blk_sum(u[tid] * u[tid], red, tid));
        if (it == 2 && tid == 0) {
            float sig = nu * nu / (nu + 1e-8f);
            g_scale = 0.99f / (sig + 1e-8f);
        }
        u[tid] = u[tid] / (nu + 1e-8f);
        __syncthreads();
    }
}

/* =========== prep: W16 = fp16(scale * W_h), after spectral =============== */
__global__ void prep_w16_kernel(const float* __restrict__ Wh) {
    int i = blockIdx.x * 1024 + threadIdx.x;
    g_Wh16[i] = __float2half_rn(g_scale * Wh[i]);
}

/* ============================ init / reset =============================== */
__global__ void init_kernel(const float* __restrict__ h0, float* __restrict__ out_h) {
    int i = blockIdx.x * blockDim.x + threadIdx.x;
    if (i < BD) {
        float v = h0[i];
        out_h[i] = v;
        g_h16[i] = __float2half_rn(v);
    }
    if (i < GRP) g_cnt4[i * 32] = 0u;
}
__global__ void reset_kernel() {
    int i = threadIdx.x;
    if (i < GRP) g_cnt4[i * 32] = 0u;
}

/* ===================== tf32 tensor-core GEMM ============================= */
template <int MODE>
__global__ void __launch_bounds__(256, 2)
gemm_kernel(const float* __restrict__ Ag, const float* __restrict__ Bg,
            float* __restrict__ Cg, const float* __restrict__ bias,
            const float* __restrict__ Zg, const float* __restrict__ Hg,
            int m_off) {
    __shared__ unsigned As[128][36];
    __shared__ unsigned Bs[128][36];
    int tid = threadIdx.x, lane = tid & 31, wid = tid >> 5;
    int wm = wid >> 1, wn = wid & 1;
    int m0 = m_off + blockIdx.x * 128, n0 = blockIdx.y * 128;

    float acc[2][8][4];
    #pragma unroll
    for (int mt = 0; mt < 2; mt++)
        #pragma unroll
        for (int nt = 0; nt < 8; nt++)
            #pragma unroll
            for (int i = 0; i < 4; i++) acc[mt][nt][i] = 0.f;

    float4 abuf[4], bbuf[4];
    #pragma unroll
    for (int f = 0; f < 4; f++) {
        int q = f * 256 + tid, row = q >> 3, c4 = q & 7;
        abuf[f] = *(const float4*)&Ag[(size_t)(m0 + row) * DD + c4 * 4];
        bbuf[f] = *(const float4*)&Bg[(size_t)(n0 + row) * DD + c4 * 4];
    }

    for (int c = 0; c < 32; c++) {
        #pragma unroll
        for (int f = 0; f < 4; f++) {
            int q = f * 256 + tid, row = q >> 3, cc = (q & 7) * 4;
            *(uint4*)&As[row][cc] = make_uint4(f2tf(abuf[f].x), f2tf(abuf[f].y),
                                               f2tf(abuf[f].z), f2tf(abuf[f].w));
            *(uint4*)&Bs[row][cc] = make_uint4(f2tf(bbuf[f].x), f2tf(bbuf[f].y),
                                               f2tf(bbuf[f].z), f2tf(bbuf[f].w));
        }
        __syncthreads();
        if (c < 31) {
            int k0 = (c + 1) * 32;
            #pragma unroll
            for (int f = 0; f < 4; f++) {
                int q = f * 256 + tid, row = q >> 3, c4 = q & 7;
                abuf[f] = *(const float4*)&Ag[(size_t)(m0 + row) * DD + k0 + c4 * 4];
                bbuf[f] = *(const float4*)&Bg[(size_t)(n0 + row) * DD + k0 + c4 * 4];
            }
        }
        #pragma unroll
        for (int kk = 0; kk < 4; kk++) {
            unsigned a[2][4];
            int ar = wm * 32 + (lane >> 2);
            int kc = kk * 8 + (lane & 3);
            #pragma unroll
            for (int mt = 0; mt < 2; mt++) {
                int r = ar + mt * 16;
                a[mt][0] = As[r][kc];
                a[mt][1] = As[r + 8][kc];
                a[mt][2] = As[r][kc + 4];
                a[mt][3] = As[r + 8][kc + 4];
            }
            #pragma unroll
            for (int nt = 0; nt < 8; nt++) {
                int nc = wn * 64 + nt * 8 + (lane >> 2);
                unsigned b0 = Bs[nc][kc];
                unsigned b1 = Bs[nc][kc + 4];
                mma_tf32(acc[0][nt], a[0], b0, b1);
                mma_tf32(acc[1][nt], a[1], b0, b1);
            }
        }
        __syncthreads();
    }

    #pragma unroll
    for (int mt = 0; mt < 2; mt++) {
        int r = m0 + wm * 32 + mt * 16 + (lane >> 2);
        #pragma unroll
        for (int nt = 0; nt < 8; nt++) {
            int cc = n0 + wn * 64 + nt * 8 + (lane & 3) * 2;
            #pragma unroll
            for (int half = 0; half < 2; half++) {
                int rr = r + half * 8;
                size_t i0 = (size_t)rr * DD + cc;
                float v0 = acc[mt][nt][half * 2 + 0];
                float v1 = acc[mt][nt][half * 2 + 1];
                if (MODE == 0) {
                    g_A[i0]     = v0 + __ldg(&bias[cc]);
                    g_A[i0 + 1] = v1 + __ldg(&bias[cc + 1]);
                } else {
                    float h0v = Hg[i0], h1v = Hg[i0 + 1];
                    float g0 = 1.0f / (1.0f + __expf(-(Zg[i0] + v0)));
                    float g1 = 1.0f / (1.0f + __expf(-(Zg[i0 + 1] + v1)));
                    Cg[i0]     = h0v * g0;
                    Cg[i0 + 1] = h1v * g1;
                }
            }
        }
    }
}

/* ================ persistent fp16 tensor-core scan ======================= */
/* 128 blocks = 4 groups x 32. Group g: batches 4g..4g+3 (N-cols 0..3 of    */
/* mma n=8 tile; cols 4-7 are discarded garbage).                           */
/* Block: 32 rows x 4 batches x full K. Warp (rt = wid&1, kq = wid>>1):     */
/* 16 rows x 256 K -> 16 mma.m16n8k16 with W fragments loop-invariant in    */
/* registers (64 regs). h: fp16 shadow buffer staged to smem each step;     */
/* B fragments via broadcast conflict-free LDS (batch stride 516 words).    */
/* K summed inside mma -> NO shuffle reduce. K-quarter partials combined    */
/* through padded smem; 128-thread output phase, coalesced stores.          */
__global__ void __launch_bounds__(256, 1)
scan_kernel(float* __restrict__ out_h) {
    __shared__ __align__(16) __half hs16[4 * 1032];   /* 4 x (1024+8) halfs */
    __shared__ float comb[2 * 4 * 4 * 17];            /* [rt][kq][b][17]    */
    int tid = threadIdx.x, lane = tid & 31, wid = tid >> 5;
    int gid = blockIdx.x >> 5;         /* group 0..3 */
    int bin = blockIdx.x & 31;         /* block within group */
    int rt  = wid & 1;                 /* row-tile 0/1 */
    int kq  = wid >> 1;                /* K-quarter 0..3 */
    int r0  = bin * 32 + rt * 16;      /* warp's 16 rows */
    int gb  = gid * 4;                 /* batch base */
    int gr  = lane >> 2, t4 = lane & 3;

    /* loop-invariant A fragments: W16[16 rows x 256 K] -> 16 mma x 4 regs */
    unsigned wf[16][4];
    {
        const __half* wra = g_Wh16 + (size_t)(r0 + gr) * DD + kq * 256 + 2 * t4;
        const __half* wrb = wra + (size_t)8 * DD;
        #pragma unroll
        for (int m = 0; m < 16; m++) {
            wf[m][0] = *(const unsigned*)(wra + m * 16);
            wf[m][1] = *(const unsigned*)(wrb + m * 16);
            wf[m][2] = *(const unsigned*)(wra + m * 16 + 8);
            wf[m][3] = *(const unsigned*)(wrb + m * 16 + 8);
        }
    }

    unsigned* cnt = &g_cnt4[gid * 32];

    /* output-phase constants (threads 0..127 produce one h value each) */
    int b_o  = tid >> 5;               /* batch 0..3 (tid<128) */
    int rl   = tid & 31;               /* local row 0..31 */
    int rt_o = rl >> 4, r_o = rl & 15;
    size_t oidx = (size_t)(gb + b_o) * DD + (bin * 32 + rl);

    /* B-fragment smem word index (broadcast for lanes 16-31) */
    int n4 = gr & 3;
    const unsigned* hsw = (const unsigned*)hs16;
    int bbase = n4 * 516 + kq * 128 + t4;

    float a_val = (tid < 128) ? __ldcg(&g_A[oidx]) : 0.f;

    for (int t = 0; t < TT; t++) {
        /* stage h16 tile (4 batches x 1024 halfs = 8KB) into smem */
        {
            const __half* hsrc = g_h16 + (size_t)t * BD + (size_t)gb * DD;
            int c0 = tid, c1 = tid + 256;
            uint4 v0 = *(const uint4*)(hsrc + (c0 >> 7) * DD + (c0 & 127) * 8);
            uint4 v1 = *(const uint4*)(hsrc + (c1 >> 7) * DD + (c1 & 127) * 8);
            *(uint4*)(hs16 + (c0 >> 7) * 1032 + (c0 & 127) * 8) = v0;
            *(uint4*)(hs16 + (c1 >> 7) * 1032 + (c1 & 127) * 8) = v1;
        }
        __syncthreads();

        /* prefetch next step's additive term */
        float a_next = 0.f;
        if (t + 1 < TT && tid < 128)
            a_next = __ldcg(&g_A[(size_t)(t + 1) * BD + oidx]);

        /* 16 mma, two independent accumulator chains */
        float ce[4] = {0.f, 0.f, 0.f, 0.f};
        float co[4] = {0.f, 0.f, 0.f, 0.f};
        #pragma unroll
        for (int m = 0; m < 16; m += 2) {
            unsigned b0 = hsw[bbase + m * 8];
            unsigned b1 = hsw[bbase + m * 8 + 4];
            mma_fp16(ce, wf[m], b0, b1);
            unsigned b2 = hsw[bbase + (m + 1) * 8];
            unsigned b3 = hsw[bbase + (m + 1) * 8 + 4];
            mma_fp16(co, wf[m + 1], b2, b3);
        }

        /* write valid fragment lanes to comb: rows gr, gr+8; cols 2t4,2t4+1 */
        if (t4 < 2) {
            int cb = (rt * 4 + kq) * 4 + 2 * t4;
            comb[(cb    ) * 17 + gr    ] = ce[0] + co[0];
            comb[(cb + 1) * 17 + gr    ] = ce[1] + co[1];
            comb[(cb    ) * 17 + gr + 8] = ce[2] + co[2];
            comb[(cb + 1) * 17 + gr + 8] = ce[3] + co[3];
        }
        __syncthreads();

        /* output: sum 4 K-quarters, tanh, dual store (fp32 + fp16 shadow) */
        if (tid < 128) {
            float tot = comb[((rt_o * 4 + 0) * 4 + b_o) * 17 + r_o]
                      + comb[((rt_o * 4 + 1) * 4 + b_o) * 17 + r_o]
                      + comb[((rt_o * 4 + 2) * 4 + b_o) * 17 + r_o]
                      + comb[((rt_o * 4 + 3) * 4 + b_o) * 17 + r_o];
            float hv = fast_tanh(tot + a_val);
            out_h[(size_t)(t + 1) * BD + oidx] = hv;
            g_h16[(size_t)(t + 1) * BD + oidx] = __float2half_rn(hv);
        }

        /* group barrier: release-arrive + acquire-poll (R7 protocol) */
        if (t + 1 < TT) {
            __syncthreads();
            if (tid == 0) {
                red_release_add(cnt);
                unsigned target = (unsigned)(t + 1) * (unsigned)BPG;
                while (ld_acquire(cnt) < target) { }
            }
            __syncthreads();
        }
        a_val = a_next;
    }
}

/* ================== host-side numpy-exact randn(1024) ==================== */
static void host_randn1024(float* out) {
    static unsigned mt[624];
    int pos;
    {
        unsigned s = 0u;
        for (int i = 0; i < 624; i++) {
            mt[i] = s;
            s = 1812433253u * (s ^ (s >> 30)) + (unsigned)(i + 1);
        }
        pos = 624;
    }
    auto next = [&]() -> unsigned {
        if (pos == 624) {
            for (int i = 0; i < 624; i++) {
                unsigned y = (mt[i] & 0x80000000u) | (mt[(i + 1) % 624] & 0x7fffffffu);
                mt[i] = mt[(i + 397) % 624] ^ (y >> 1) ^ ((y & 1u) ? 0x9908b0dfu : 0u);
            }
            pos = 0;
        }
        unsigned y = mt[pos++];
        y ^= y >> 11;
        y ^= (y << 7) & 0x9d2c5680u;
        y ^= (y << 15) & 0xefc60000u;
        y ^= y >> 18;
        return y;
    };
    auto nextDouble = [&]() -> double {
        unsigned a = next() >> 5, b = next() >> 6;
        return ((double)a * 67108864.0 + (double)b) / 9007199254740992.0;
    };
    bool has_g = false;
    double gcache = 0.0;
    for (int i = 0; i < DD; i++) {
        double val;
        if (has_g) { val = gcache; has_g = false; }
        else {
            double x1, x2, r2;
            do {
                x1 = 2.0 * nextDouble() - 1.0;
                x2 = 2.0 * nextDouble() - 1.0;
                r2 = x1 * x1 + x2 * x2;
            } while (r2 >= 1.0 || r2 == 0.0);
            double f = sqrt(-2.0 * log(r2) / r2);
            gcache = f * x1; has_g = true; val = f * x2;
        }
        out[i] = (float)val;
    }
}

/* ============================== launcher ================================= */
extern "C" void kernel_launch(void* const* d_in, const int* in_sizes, int n_in,
                              void* d_out, int out_size) {
    const float* x    = (const float*)d_in[0];
    const float* z    = (const float*)d_in[1];
    const float* h0   = (const float*)d_in[2];
    const float* Wx   = (const float*)d_in[3];
    const float* Wh   = (const float*)d_in[4];
    const float* Wg   = (const float*)d_in[5];
    const float* bias = (const float*)d_in[6];

    float* out   = (float*)d_out;
    float* outs  = out;                          /* [T, B, D]   */
    float* out_h = out + (size_t)NROW * DD;      /* [T+1, B, D] */
    const float* hs = out_h + BD;                /* h[1..T], row = t*B+b */

    static float u_host[DD];
    host_randn1024(u_host);
    P1024 u0;
    for (int i = 0; i < DD; i++) u0.v[i] = u_host[i];

    /* launch order fixed so ncu (-s 5 -c 1) lands inside the hot section */
    spectral_kernel<<<1, 1024>>>(Wh, u0);                                     /* 0 */
    prep_w16_kernel<<<1024, 1024>>>(Wh);                                      /* 1 */
    init_kernel<<<16, 1024>>>(h0, out_h);                                     /* 2 */
    gemm_kernel<0><<<dim3(128, 8), 256>>>(x, Wx, nullptr, bias,
                                          nullptr, nullptr, 0);               /* 3 */
    gemm_kernel<0><<<dim3(128, 8), 256>>>(x, Wx, nullptr, bias,
                                          nullptr, nullptr, 16384);           /* 4 */
    reset_kernel<<<1, 32>>>();                                                /* 5 */
    scan_kernel<<<SNB, 256>>>(out_h);                                         /* 6 */
    gemm_kernel<1><<<dim3(256, 8), 256>>>(hs, Wg, outs, nullptr,
                                          z, hs, 0);                          /* 7 */
}

// round 10
// speedup vs baseline: 3.3171x; 1.0963x over previous
#include <cuda_runtime.h>
#include <cuda_fp16.h>
#include <math.h>

#define DD   1024
#define BB   16
#define TT   2048
#define NROW (TT*BB)          /* 32768 */
#define BD   (BB*DD)          /* 16384 */
#define SNB  128              /* scan blocks total */
#define GRP  4                /* independent batch groups */
#define BPG  32               /* blocks per group */

/* ------------- static device scratch (no allocations allowed) ------------- */
__device__ float    g_A[33554432];            /* x@Wx^T + b, [T*B, D], 128MB */
__device__ float    g_scale;                  /* 0.99/(sigma+eps) */
__device__ unsigned g_cnt4[GRP * 32];         /* one 128B line per group */
__device__ __half   g_Wh16[DD * DD];          /* fp16 of (scale * W_h), 2MB */
__device__ __half   g_h16[(TT + 1) * BD];     /* fp16 shadow of h, 67MB */

/* ====================== small PTX helpers ================================ */
__device__ __forceinline__ void mma_fp16(float* c, const unsigned* a,
                                         unsigned b0, unsigned b1) {
    asm volatile(
        "mma.sync.aligned.m16n8k16.row.col.f32.f16.f16.f32 "
        "{%0,%1,%2,%3},{%4,%5,%6,%7},{%8,%9},{%0,%1,%2,%3};"
        : "+f"(c[0]), "+f"(c[1]), "+f"(c[2]), "+f"(c[3])
        : "r"(a[0]), "r"(a[1]), "r"(a[2]), "r"(a[3]), "r"(b0), "r"(b1));
}
/* fire-and-forget release arrive */
__device__ __forceinline__ void red_release_add(unsigned* p) {
    asm volatile("red.release.gpu.global.add.u32 [%0], 1;" :: "l"(p) : "memory");
}
__device__ __forceinline__ unsigned ld_acquire(const unsigned* p) {
    unsigned v;
    asm volatile("ld.acquire.gpu.global.u32 %0, [%1];" : "=r"(v) : "l"(p) : "memory");
    return v;
}
/* overflow-free fast tanh */
__device__ __forceinline__ float fast_tanh(float x) {
    float e = __expf(-2.0f * fabsf(x));
    float r = __fdividef(1.0f - e, 1.0f + e);
    return copysignf(r, x);
}
__device__ __forceinline__ unsigned pack_h2(float lo, float hi) {
    __half2 p = __floats2half2_rn(lo, hi);
    return *(unsigned*)&p;
}

/* ===================== block-wide sum reduce ============================= */
__device__ __forceinline__ float blk_sum(float x, float* red, int tid) {
    #pragma unroll
    for (int o = 16; o; o >>= 1) x += __shfl_xor_sync(0xffffffffu, x, o);
    if ((tid & 31) == 0) red[tid >> 5] = x;
    __syncthreads();
    if (tid < 32) {
        float r = (tid < (int)(blockDim.x >> 5)) ? red[tid] : 0.f;
        #pragma unroll
        for (int o = 16; o; o >>= 1) r += __shfl_xor_sync(0xffffffffu, r, o);
        if (tid == 0) red[0] = r;
    }
    __syncthreads();
    float r = red[0];
    __syncthreads();
    return r;
}

/* ==================== fused spectral normalization ======================= */
struct P1024 { float v[1024]; };

__global__ void spectral_kernel(const float* __restrict__ Wh, P1024 u0) {
    __shared__ float u[DD], v[DD];
    __shared__ float red[32];
    int tid = threadIdx.x, lane = tid & 31, wid = tid >> 5;

    float x = u0.v[tid];
    float n0 = sqrtf(blk_sum(x * x, red, tid));   /* no eps: matches ref init */
    u[tid] = x / n0;
    __syncthreads();

    for (int it = 0; it < 3; it++) {
        float s = 0.f;
        #pragma unroll 4
        for (int k = 0; k < DD; k++) s = fmaf(__ldg(&Wh[(size_t)k * DD + tid]), u[k], s);
        float nv = sqrtf(blk_sum(s * s, red, tid)) + 1e-8f;
        v[tid] = s / nv;
        __syncthreads();

        for (int r = wid; r < DD; r += 32) {
            float p = 0.f;
            const float4* W4 = (const float4*)(Wh + (size_t)r * DD);
            const float4* v4 = (const float4*)v;
            #pragma unroll
            for (int i2 = 0; i2 < 8; i2++) {
                float4 w = __ldg(&W4[i2 * 32 + lane]);
                float4 vv = v4[i2 * 32 + lane];
                p = fmaf(w.x, vv.x, p); p = fmaf(w.y, vv.y, p);
                p = fmaf(w.z, vv.z, p); p = fmaf(w.w, vv.w, p);
            }
            #pragma unroll
            for (int o = 16; o; o >>= 1) p += __shfl_xor_sync(0xffffffffu, p, o);
            if (lane == 0) u[r] = p;
        }
        __syncthreads();
        float nu = sqrtf(blk_sum(u[tid] * u[tid], red, tid));
        if (it == 2 && tid == 0) {
            float sig = nu * nu / (nu + 1e-8f);
            g_scale = 0.99f / (sig + 1e-8f);
        }
        u[tid] = u[tid] / (nu + 1e-8f);
        __syncthreads();
    }
}

/* =========== prep: W16 = fp16(scale * W_h), after spectral =============== */
__global__ void prep_w16_kernel(const float* __restrict__ Wh) {
    int i = blockIdx.x * 1024 + threadIdx.x;
    g_Wh16[i] = __float2half_rn(g_scale * Wh[i]);
}

/* ============================ init / reset =============================== */
__global__ void init_kernel(const float* __restrict__ h0, float* __restrict__ out_h) {
    int i = blockIdx.x * blockDim.x + threadIdx.x;
    if (i < BD) {
        float v = h0[i];
        out_h[i] = v;
        g_h16[i] = __float2half_rn(v);
    }
    if (i < GRP) g_cnt4[i * 32] = 0u;
}
__global__ void reset_kernel() {
    int i = threadIdx.x;
    if (i < GRP) g_cnt4[i * 32] = 0u;
}

/* ===================== fp16 tensor-core GEMM ============================= */
/* C[M,N] = A[M,K]*B[N,K]^T, 128x128 tile, 8 warps, mma.m16n8k16 (half the  */
/* HMMA count of tf32 k8 at the SAME 10-bit-mantissa precision).            */
/* smem: half2 words, row stride 20 (conflict-free: 20*gr+t4 distinct %32). */
/* MODE 0: A = Ag_ fp32 (convert in-kernel); g_A = acc + bias[n]            */
/* MODE 1: A = g_h16+BD fp16 (device symbol); Cg = Hg * sigmoid(Zg + acc)   */
template <int MODE>
__global__ void __launch_bounds__(256, 2)
gemm16_kernel(const float* __restrict__ Ag_, const float* __restrict__ Bg,
              float* __restrict__ Cg, const float* __restrict__ bias,
              const float* __restrict__ Zg, const float* __restrict__ Hg,
              int m_off) {
    __shared__ unsigned As[128][20];
    __shared__ unsigned Bs[128][20];
    int tid = threadIdx.x, lane = tid & 31, wid = tid >> 5;
    int gr = lane >> 2, t4 = lane & 3;
    int wm = wid >> 1, wn = wid & 1;
    int m0 = m_off + blockIdx.x * 128, n0 = blockIdx.y * 128;
    const float*  Af = Ag_;
    const __half* Ah = g_h16 + BD;    /* MODE 1: h[1..T] fp16 shadow */

    float acc[2][8][4];
    #pragma unroll
    for (int mt = 0; mt < 2; mt++)
        #pragma unroll
        for (int nt = 0; nt < 8; nt++)
            #pragma unroll
            for (int i = 0; i < 4; i++) acc[mt][nt][i] = 0.f;

    float4 abuf[4]; uint4 abuf16[2]; float4 bbuf[4];
    /* prefetch k-tile 0 */
    if (MODE == 0) {
        #pragma unroll
        for (int f = 0; f < 4; f++) {
            int q = f * 256 + tid, row = q >> 3, c4 = q & 7;
            abuf[f] = *(const float4*)&Af[(size_t)(m0 + row) * DD + c4 * 4];
        }
    } else {
        #pragma unroll
        for (int f = 0; f < 2; f++) {
            int q = f * 256 + tid, row = q >> 2, c8 = q & 3;
            abuf16[f] = *(const uint4*)(Ah + (size_t)(m0 + row) * DD + c8 * 8);
        }
    }
    #pragma unroll
    for (int f = 0; f < 4; f++) {
        int q = f * 256 + tid, row = q >> 3, c4 = q & 7;
        bbuf[f] = *(const float4*)&Bg[(size_t)(n0 + row) * DD + c4 * 4];
    }

    for (int c = 0; c < 32; c++) {
        /* store current k-tile to smem as half2 words */
        if (MODE == 0) {
            #pragma unroll
            for (int f = 0; f < 4; f++) {
                int q = f * 256 + tid, row = q >> 3, c4 = q & 7;
                *(uint2*)&As[row][c4 * 2] =
                    make_uint2(pack_h2(abuf[f].x, abuf[f].y),
                               pack_h2(abuf[f].z, abuf[f].w));
            }
        } else {
            #pragma unroll
            for (int f = 0; f < 2; f++) {
                int q = f * 256 + tid, row = q >> 2, c8 = q & 3;
                *(uint4*)&As[row][c8 * 4] = abuf16[f];
            }
        }
        #pragma unroll
        for (int f = 0; f < 4; f++) {
            int q = f * 256 + tid, row = q >> 3, c4 = q & 7;
            *(uint2*)&Bs[row][c4 * 2] =
                make_uint2(pack_h2(bbuf[f].x, bbuf[f].y),
                           pack_h2(bbuf[f].z, bbuf[f].w));
        }
        __syncthreads();
        if (c < 31) {
            int k0 = (c + 1) * 32;
            if (MODE == 0) {
                #pragma unroll
                for (int f = 0; f < 4; f++) {
                    int q = f * 256 + tid, row = q >> 3, c4 = q & 7;
                    abuf[f] = *(const float4*)&Af[(size_t)(m0 + row) * DD + k0 + c4 * 4];
                }
            } else {
                #pragma unroll
                for (int f = 0; f < 2; f++) {
                    int q = f * 256 + tid, row = q >> 2, c8 = q & 3;
                    abuf16[f] = *(const uint4*)(Ah + (size_t)(m0 + row) * DD + k0 + c8 * 8);
                }
            }
            #pragma unroll
            for (int f = 0; f < 4; f++) {
                int q = f * 256 + tid, row = q >> 3, c4 = q & 7;
                bbuf[f] = *(const float4*)&Bg[(size_t)(n0 + row) * DD + k0 + c4 * 4];
            }
        }
        #pragma unroll
        for (int ks = 0; ks < 2; ks++) {
            int aw = t4 + ks * 8;
            unsigned a[2][4];
            #pragma unroll
            for (int mt = 0; mt < 2; mt++) {
                int r = wm * 32 + mt * 16 + gr;
                a[mt][0] = As[r][aw];
                a[mt][1] = As[r + 8][aw];
                a[mt][2] = As[r][aw + 4];
                a[mt][3] = As[r + 8][aw + 4];
            }
            #pragma unroll
            for (int nt = 0; nt < 8; nt++) {
                int nc = wn * 64 + nt * 8 + gr;
                unsigned b0 = Bs[nc][aw];
                unsigned b1 = Bs[nc][aw + 4];
                mma_fp16(acc[0][nt], a[0], b0, b1);
                mma_fp16(acc[1][nt], a[1], b0, b1);
            }
        }
        __syncthreads();
    }

    /* epilogue (C fragment layout identical to k8 case) */
    #pragma unroll
    for (int mt = 0; mt < 2; mt++) {
        int r = m0 + wm * 32 + mt * 16 + gr;
        #pragma unroll
        for (int nt = 0; nt < 8; nt++) {
            int cc = n0 + wn * 64 + nt * 8 + t4 * 2;
            #pragma unroll
            for (int half = 0; half < 2; half++) {
                int rr = r + half * 8;
                size_t i0 = (size_t)rr * DD + cc;
                float v0 = acc[mt][nt][half * 2 + 0];
                float v1 = acc[mt][nt][half * 2 + 1];
                if (MODE == 0) {
                    g_A[i0]     = v0 + __ldg(&bias[cc]);
                    g_A[i0 + 1] = v1 + __ldg(&bias[cc + 1]);
                } else {
                    float h0v = Hg[i0], h1v = Hg[i0 + 1];
                    float g0 = 1.0f / (1.0f + __expf(-(Zg[i0] + v0)));
                    float g1 = 1.0f / (1.0f + __expf(-(Zg[i0 + 1] + v1)));
                    Cg[i0]     = h0v * g0;
                    Cg[i0 + 1] = h1v * g1;
                }
            }
        }
    }
}

/* ================ persistent fp16 tensor-core scan ======================= */
/* 128 blocks = 4 groups x 32; warp = 16 rows x 256 K -> 16 mma.m16n8k16.   */
/* fp32 out_h store deferred until AFTER the barrier so the release only    */
/* drains the fp16 shadow stores (the recurrence's real data).              */
__global__ void __launch_bounds__(256, 1)
scan_kernel(float* __restrict__ out_h) {
    __shared__ __align__(16) __half hs16[4 * 1032];   /* 4 x (1024+8) halfs */
    __shared__ float comb[2 * 4 * 4 * 17];            /* [rt][kq][b][17]    */
    int tid = threadIdx.x, lane = tid & 31, wid = tid >> 5;
    int gid = blockIdx.x >> 5;         /* group 0..3 */
    int bin = blockIdx.x & 31;         /* block within group */
    int rt  = wid & 1;                 /* row-tile 0/1 */
    int kq  = wid >> 1;                /* K-quarter 0..3 */
    int r0  = bin * 32 + rt * 16;      /* warp's 16 rows */
    int gb  = gid * 4;                 /* batch base */
    int gr = lane >> 2, t4 = lane & 3;

    /* loop-invariant A fragments: W16[16 rows x 256 K] -> 16 mma x 4 regs */
    unsigned wf[16][4];
    {
        const __half* wra = g_Wh16 + (size_t)(r0 + gr) * DD + kq * 256 + 2 * t4;
        const __half* wrb = wra + (size_t)8 * DD;
        #pragma unroll
        for (int m = 0; m < 16; m++) {
            wf[m][0] = *(const unsigned*)(wra + m * 16);
            wf[m][1] = *(const unsigned*)(wrb + m * 16);
            wf[m][2] = *(const unsigned*)(wra + m * 16 + 8);
            wf[m][3] = *(const unsigned*)(wrb + m * 16 + 8);
        }
    }

    unsigned* cnt = &g_cnt4[gid * 32];

    /* output-phase constants (threads 0..127 produce one h value each) */
    int b_o  = tid >> 5;               /* batch 0..3 (tid<128) */
    int rl   = tid & 31;               /* local row 0..31 */
    int rt_o = rl >> 4, r_o = rl & 15;
    size_t oidx = (size_t)(gb + b_o) * DD + (bin * 32 + rl);

    /* B-fragment smem word index (broadcast for lanes 16-31) */
    int n4 = gr & 3;
    const unsigned* hsw = (const unsigned*)hs16;
    int bbase = n4 * 516 + kq * 128 + t4;

    float a_val = (tid < 128) ? __ldcg(&g_A[oidx]) : 0.f;

    for (int t = 0; t < TT; t++) {
        /* stage h16 tile (4 batches x 1024 halfs = 8KB) into smem */
        {
            const __half* hsrc = g_h16 + (size_t)t * BD + (size_t)gb * DD;
            int c0 = tid, c1 = tid + 256;
            uint4 v0 = *(const uint4*)(hsrc + (c0 >> 7) * DD + (c0 & 127) * 8);
            uint4 v1 = *(const uint4*)(hsrc + (c1 >> 7) * DD + (c1 & 127) * 8);
            *(uint4*)(hs16 + (c0 >> 7) * 1032 + (c0 & 127) * 8) = v0;
            *(uint4*)(hs16 + (c1 >> 7) * 1032 + (c1 & 127) * 8) = v1;
        }
        __syncthreads();

        /* prefetch next step's additive term */
        float a_next = 0.f;
        if (t + 1 < TT && tid < 128)
            a_next = __ldcg(&g_A[(size_t)(t + 1) * BD + oidx]);

        /* 16 mma, two independent accumulator chains */
        float ce[4] = {0.f, 0.f, 0.f, 0.f};
        float co[4] = {0.f, 0.f, 0.f, 0.f};
        #pragma unroll
        for (int m = 0; m < 16; m += 2) {
            unsigned b0 = hsw[bbase + m * 8];
            unsigned b1 = hsw[bbase + m * 8 + 4];
            mma_fp16(ce, wf[m], b0, b1);
            unsigned b2 = hsw[bbase + (m + 1) * 8];
            unsigned b3 = hsw[bbase + (m + 1) * 8 + 4];
            mma_fp16(co, wf[m + 1], b2, b3);
        }

        /* write valid fragment lanes to comb: rows gr, gr+8; cols 2t4,2t4+1 */
        if (t4 < 2) {
            int cb = (rt * 4 + kq) * 4 + 2 * t4;
            comb[(cb    ) * 17 + gr    ] = ce[0] + co[0];
            comb[(cb + 1) * 17 + gr    ] = ce[1] + co[1];
            comb[(cb    ) * 17 + gr + 8] = ce[2] + co[2];
            comb[(cb + 1) * 17 + gr + 8] = ce[3] + co[3];
        }
        __syncthreads();

        /* output: sum 4 K-quarters, tanh, store fp16 shadow ONLY before    */
        /* the release; fp32 copy deferred past the barrier                 */
        float hv = 0.f;
        if (tid < 128) {
            float tot = comb[((rt_o * 4 + 0) * 4 + b_o) * 17 + r_o]
                      + comb[((rt_o * 4 + 1) * 4 + b_o) * 17 + r_o]
                      + comb[((rt_o * 4 + 2) * 4 + b_o) * 17 + r_o]
                      + comb[((rt_o * 4 + 3) * 4 + b_o) * 17 + r_o];
            hv = fast_tanh(tot + a_val);
            g_h16[(size_t)(t + 1) * BD + oidx] = __float2half_rn(hv);
        }

        /* group barrier: release-arrive + acquire-poll */
        if (t + 1 < TT) {
            __syncthreads();
            if (tid == 0) {
                red_release_add(cnt);
                unsigned target = (unsigned)(t + 1) * (unsigned)BPG;
                while (ld_acquire(cnt) < target) { }
            }
            __syncthreads();
        }

        /* deferred fp32 store — off the release critical path (nothing     */
        /* reads out_h during the scan) */
        if (tid < 128)
            out_h[(size_t)(t + 1) * BD + oidx] = hv;

        a_val = a_next;
    }
}

/* ================== host-side numpy-exact randn(1024) ==================== */
static void host_randn1024(float* out) {
    static unsigned mt[624];
    int pos;
    {
        unsigned s = 0u;
        for (int i = 0; i < 624; i++) {
            mt[i] = s;
            s = 1812433253u * (s ^ (s >> 30)) + (unsigned)(i + 1);
        }
        pos = 624;
    }
    auto next = [&]() -> unsigned {
        if (pos == 624) {
            for (int i = 0; i < 624; i++) {
                unsigned y = (mt[i] & 0x80000000u) | (mt[(i + 1) % 624] & 0x7fffffffu);
                mt[i] = mt[(i + 397) % 624] ^ (y >> 1) ^ ((y & 1u) ? 0x9908b0dfu : 0u);
            }
            pos = 0;
        }
        unsigned y = mt[pos++];
        y ^= y >> 11;
        y ^= (y << 7) & 0x9d2c5680u;
        y ^= (y << 15) & 0xefc60000u;
        y ^= y >> 18;
        return y;
    };
    auto nextDouble = [&]() -> double {
        unsigned a = next() >> 5, b = next() >> 6;
        return ((double)a * 67108864.0 + (double)b) / 9007199254740992.0;
    };
    bool has_g = false;
    double gcache = 0.0;
    for (int i = 0; i < DD; i++) {
        double val;
        if (has_g) { val = gcache; has_g = false; }
        else {
            double x1, x2, r2;
            do {
                x1 = 2.0 * nextDouble() - 1.0;
                x2 = 2.0 * nextDouble() - 1.0;
                r2 = x1 * x1 + x2 * x2;
            } while (r2 >= 1.0 || r2 == 0.0);
            double f = sqrt(-2.0 * log(r2) / r2);
            gcache = f * x1; has_g = true; val = f * x2;
        }
        out[i] = (float)val;
    }
}

/* ============================== launcher ================================= */
extern "C" void kernel_launch(void* const* d_in, const int* in_sizes, int n_in,
                              void* d_out, int out_size) {
    const float* x    = (const float*)d_in[0];
    const float* z    = (const float*)d_in[1];
    const float* h0   = (const float*)d_in[2];
    const float* Wx   = (const float*)d_in[3];
    const float* Wh   = (const float*)d_in[4];
    const float* Wg   = (const float*)d_in[5];
    const float* bias = (const float*)d_in[6];

    float* out   = (float*)d_out;
    float* outs  = out;                          /* [T, B, D]   */
    float* out_h = out + (size_t)NROW * DD;      /* [T+1, B, D] */
    const float* hs = out_h + BD;                /* h[1..T], row = t*B+b */

    static float u_host[DD];
    host_randn1024(u_host);
    P1024 u0;
    for (int i = 0; i < DD; i++) u0.v[i] = u_host[i];

    /* launch order fixed so ncu (-s 5 -c 1) captures the scan kernel */
    spectral_kernel<<<1, 1024>>>(Wh, u0);                                     /* 0 */
    prep_w16_kernel<<<1024, 1024>>>(Wh);                                      /* 1 */
    init_kernel<<<16, 1024>>>(h0, out_h);                                     /* 2 */
    gemm16_kernel<0><<<dim3(256, 8), 256>>>(x, Wx, nullptr, bias,
                                            nullptr, nullptr, 0);             /* 3 */
    reset_kernel<<<1, 32>>>();                                                /* 4 */
    scan_kernel<<<SNB, 256>>>(out_h);                                         /* 5 */
    gemm16_kernel<1><<<dim3(256, 8), 256>>>(nullptr, Wg, outs, nullptr,
                                            z, hs, 0);                        /* 6 */
}